// round 8
// baseline (speedup 1.0000x reference)
#include <cuda_runtime.h>

#define BATCH   8
#define NPATCH  784
#define EDIM    384
#define NHEAD   12
#define HDIM    32
#define GRID_S  28

typedef unsigned long long ull;

// -------- scratch (no allocations allowed) --------
__device__ float g_Q[BATCH * NPATCH * EDIM];
__device__ float g_K[BATCH * NPATCH * EDIM];
__device__ float g_V[BATCH * NPATCH * EDIM];
__device__ float g_O[BATCH * NPATCH * EDIM];
__device__ float g_posO[BATCH * NHEAD * NPATCH * HDIM];

// -------- packed f32x2 helpers (sm_103a) --------
__device__ __forceinline__ ull fma2(ull a, ull b, ull c) {
    ull d;
    asm("fma.rn.f32x2 %0, %1, %2, %3;" : "=l"(d) : "l"(a), "l"(b), "l"(c));
    return d;
}
__device__ __forceinline__ ull pack2(float lo, float hi) {
    ull r;
    asm("mov.b64 %0, {%1, %2};" : "=l"(r) : "f"(lo), "f"(hi));
    return r;
}
__device__ __forceinline__ void unpack2(ull v, float& lo, float& hi) {
    asm("mov.b64 {%0, %1}, %2;" : "=f"(lo), "=f"(hi) : "l"(v));
}
__device__ __forceinline__ float ex2f(float x) {
    float y;
    asm("ex2.approx.f32 %0, %1;" : "=f"(y) : "f"(x));
    return y;
}

// =====================================================================
// GEMM (measured ~42.7us/GEMM): Y[M,384] = X[M,384] @ W^T
// 128x64 tile, 256 threads, 8x4 micro-tile, pack-in-loop.
// =====================================================================
#define GTK 16

template <bool HAS_BIAS>
__device__ __forceinline__ void gemm_tile(const float* __restrict__ X,
                                          const float* __restrict__ W,
                                          const float* __restrict__ bias,
                                          float* __restrict__ Y)
{
    __shared__ __align__(16) float As[GTK][128];
    __shared__ __align__(16) float Bs[GTK][64];

    const int t    = threadIdx.x;
    const int row0 = blockIdx.x * 128;
    const int col0 = blockIdx.y * 64;
    const int tr   = t >> 4;
    const int tc   = t & 15;

    const int arow = t >> 2;
    const int aj4  = (t & 3) << 2;
    const float* ap0 = X + (size_t)(row0 + arow) * EDIM + aj4;
    const float* ap1 = X + (size_t)(row0 + 64 + arow) * EDIM + aj4;
    const float* bp_ = W + (size_t)(col0 + arow) * EDIM + aj4;

    ull c[8][2];
#pragma unroll
    for (int r = 0; r < 8; r++) { c[r][0] = 0ull; c[r][1] = 0ull; }

    float4 ra0 = *(const float4*)(ap0);
    float4 ra1 = *(const float4*)(ap1);
    float4 rb  = *(const float4*)(bp_);

    for (int s = 0; s < EDIM / GTK; s++) {
        __syncthreads();
        As[aj4 + 0][arow] = ra0.x; As[aj4 + 1][arow] = ra0.y;
        As[aj4 + 2][arow] = ra0.z; As[aj4 + 3][arow] = ra0.w;
        As[aj4 + 0][64 + arow] = ra1.x; As[aj4 + 1][64 + arow] = ra1.y;
        As[aj4 + 2][64 + arow] = ra1.z; As[aj4 + 3][64 + arow] = ra1.w;
        Bs[aj4 + 0][arow] = rb.x; Bs[aj4 + 1][arow] = rb.y;
        Bs[aj4 + 2][arow] = rb.z; Bs[aj4 + 3][arow] = rb.w;
        __syncthreads();

        if (s + 1 < EDIM / GTK) {
            const int ko = (s + 1) * GTK;
            ra0 = *(const float4*)(ap0 + ko);
            ra1 = *(const float4*)(ap1 + ko);
            rb  = *(const float4*)(bp_ + ko);
        }

#pragma unroll
        for (int kk = 0; kk < GTK; kk++) {
            float4 a0 = *(const float4*)&As[kk][tr * 8];
            float4 a1 = *(const float4*)&As[kk][tr * 8 + 4];
            ulonglong2 bb = *(const ulonglong2*)&Bs[kk][tc * 4];
            ull A0 = pack2(a0.x, a0.x);
            ull A1 = pack2(a0.y, a0.y);
            ull A2 = pack2(a0.z, a0.z);
            ull A3 = pack2(a0.w, a0.w);
            ull A4 = pack2(a1.x, a1.x);
            ull A5 = pack2(a1.y, a1.y);
            ull A6 = pack2(a1.z, a1.z);
            ull A7 = pack2(a1.w, a1.w);
            c[0][0] = fma2(A0, bb.x, c[0][0]); c[0][1] = fma2(A0, bb.y, c[0][1]);
            c[1][0] = fma2(A1, bb.x, c[1][0]); c[1][1] = fma2(A1, bb.y, c[1][1]);
            c[2][0] = fma2(A2, bb.x, c[2][0]); c[2][1] = fma2(A2, bb.y, c[2][1]);
            c[3][0] = fma2(A3, bb.x, c[3][0]); c[3][1] = fma2(A3, bb.y, c[3][1]);
            c[4][0] = fma2(A4, bb.x, c[4][0]); c[4][1] = fma2(A4, bb.y, c[4][1]);
            c[5][0] = fma2(A5, bb.x, c[5][0]); c[5][1] = fma2(A5, bb.y, c[5][1]);
            c[6][0] = fma2(A6, bb.x, c[6][0]); c[6][1] = fma2(A6, bb.y, c[6][1]);
            c[7][0] = fma2(A7, bb.x, c[7][0]); c[7][1] = fma2(A7, bb.y, c[7][1]);
        }
    }

    const int j0 = col0 + tc * 4;
    float b0 = 0.f, b1 = 0.f, b2 = 0.f, b3 = 0.f;
    if (HAS_BIAS) {
        float4 bb = *(const float4*)(bias + j0);
        b0 = bb.x; b1 = bb.y; b2 = bb.z; b3 = bb.w;
    }
#pragma unroll
    for (int r = 0; r < 8; r++) {
        const int row = row0 + tr * 8 + r;
        float o0, o1, o2, o3;
        unpack2(c[r][0], o0, o1);
        unpack2(c[r][1], o2, o3);
        float4 o = make_float4(o0 + b0, o1 + b1, o2 + b2, o3 + b3);
        *(float4*)(Y + (size_t)row * EDIM + j0) = o;
    }
}

__global__ __launch_bounds__(256, 3) void qkv_kernel(const float* __restrict__ X,
                                                     const float* __restrict__ Wq,
                                                     const float* __restrict__ Wk,
                                                     const float* __restrict__ Wv)
{
    const float* W;
    float* Y;
    if (blockIdx.z == 0)      { W = Wq; Y = g_Q; }
    else if (blockIdx.z == 1) { W = Wk; Y = g_K; }
    else                      { W = Wv; Y = g_V; }
    gemm_tile<false>(X, W, nullptr, Y);
}

__global__ __launch_bounds__(256, 3) void out_kernel(const float* __restrict__ Wo,
                                                     const float* __restrict__ bo,
                                                     float* __restrict__ Y)
{
    gemm_tile<true>(g_O, Wo, bo, Y);
}

// =====================================================================
// Positional attention output (unchanged, validated): posO = softmax(pos)@V
// =====================================================================
__global__ __launch_bounds__(224) void pos_kernel(const float* __restrict__ Wpos,
                                                  const float* __restrict__ bpos)
{
    const int t    = threadIdx.x;
    const int qi   = t >> 1;
    const int half = t & 1;
    const int h = blockIdx.y;
    const int b = blockIdx.z;
    const int n = blockIdx.x * 112 + qi;

    const float LOG2E = 1.4426950408889634f;
    const float w0 = Wpos[h * 3 + 0];
    const float w1 = Wpos[h * 3 + 1];
    const float w2 = Wpos[h * 3 + 2];
    const float bp = bpos[h];

    const float* vbase = g_V + (size_t)b * NPATCH * EDIM + h * HDIM + half * 16;

    ull acc[8];
#pragma unroll
    for (int p = 0; p < 8; p++) acc[p] = 0ull;
    float Z;
    const ull ONE2 = pack2(1.f, 1.f);

    const float mx = fmaxf(fabsf(w0), fmaxf(fabsf(w1), fabsf(w2)));
    if (mx < 1e-12f) {
#pragma unroll 4
        for (int m = 0; m < NPATCH; m++) {
            const ulonglong2* vp = (const ulonglong2*)(vbase + (size_t)m * EDIM);
            ulonglong2 v0 = vp[0], v1 = vp[1], v2 = vp[2], v3 = vp[3];
            acc[0] = fma2(v0.x, ONE2, acc[0]); acc[1] = fma2(v0.y, ONE2, acc[1]);
            acc[2] = fma2(v1.x, ONE2, acc[2]); acc[3] = fma2(v1.y, ONE2, acc[3]);
            acc[4] = fma2(v2.x, ONE2, acc[4]); acc[5] = fma2(v2.y, ONE2, acc[5]);
            acc[6] = fma2(v3.x, ONE2, acc[6]); acc[7] = fma2(v3.y, ONE2, acc[7]);
        }
        Z = (float)NPATCH;
    } else if (fabsf(w2) > 1e-6f) {
        const float inv2   = 0.5f / w2;
        const float c2     = w2 * LOG2E;
        const float dconst = (bp - (w0 * w0 + w1 * w1) * 0.5f * inv2) * LOG2E;
        const float qx = (float)(n % GRID_S) - w0 * inv2;
        const float qy = (float)(n / GRID_S) - w1 * inv2;
        float Rf = 40.f;
        if (c2 < -1e-6f) Rf = sqrtf((46.f + fabsf(dconst)) / (-c2));
        int x0 = max(0, (int)ceilf(qx - Rf));
        int x1 = min(GRID_S - 1, (int)floorf(qx + Rf));
        int y0 = max(0, (int)ceilf(qy - Rf));
        int y1 = min(GRID_S - 1, (int)floorf(qy + Rf));
        Z = 0.f;
        for (int yy = y0; yy <= y1; yy++) {
            const float fdy = (float)yy - qy;
            const float dy2 = fdy * fdy;
            const float* vrow = vbase + (size_t)(yy * GRID_S) * EDIM;
            for (int xx = x0; xx <= x1; xx++) {
                const float fdx = (float)xx - qx;
                const float w = ex2f(fmaf(c2, fmaf(fdx, fdx, dy2), dconst));
                Z += w;
                const ull w2p = pack2(w, w);
                const ulonglong2* vp = (const ulonglong2*)(vrow + (size_t)xx * EDIM);
                ulonglong2 v0 = vp[0], v1 = vp[1], v2_ = vp[2], v3 = vp[3];
                acc[0] = fma2(w2p, v0.x, acc[0]);  acc[1] = fma2(w2p, v0.y, acc[1]);
                acc[2] = fma2(w2p, v1.x, acc[2]);  acc[3] = fma2(w2p, v1.y, acc[3]);
                acc[4] = fma2(w2p, v2_.x, acc[4]); acc[5] = fma2(w2p, v2_.y, acc[5]);
                acc[6] = fma2(w2p, v3.x, acc[6]);  acc[7] = fma2(w2p, v3.y, acc[7]);
            }
        }
    } else {
        const int qc = n % GRID_S, qr = n / GRID_S;
        Z = 0.f;
        for (int m = 0; m < NPATCH; m++) {
            const float fdx = (float)(m % GRID_S - qc);
            const float fdy = (float)(m / GRID_S - qr);
            const float lg = (fmaf(w0, fdx, fmaf(w1, fdy, w2 * fmaf(fdx, fdx, fdy * fdy))) + bp) * LOG2E;
            const float w = ex2f(lg);
            Z += w;
            const ull w2p = pack2(w, w);
            const ulonglong2* vp = (const ulonglong2*)(vbase + (size_t)m * EDIM);
            ulonglong2 v0 = vp[0], v1 = vp[1], v2_ = vp[2], v3 = vp[3];
            acc[0] = fma2(w2p, v0.x, acc[0]);  acc[1] = fma2(w2p, v0.y, acc[1]);
            acc[2] = fma2(w2p, v1.x, acc[2]);  acc[3] = fma2(w2p, v1.y, acc[3]);
            acc[4] = fma2(w2p, v2_.x, acc[4]); acc[5] = fma2(w2p, v2_.y, acc[5]);
            acc[6] = fma2(w2p, v3.x, acc[6]);  acc[7] = fma2(w2p, v3.y, acc[7]);
        }
    }

    const float inv = 1.f / Z;
    float* op = g_posO + (((size_t)(b * NHEAD + h) * NPATCH + n) * HDIM) + half * 16;
#pragma unroll
    for (int p = 0; p < 8; p++) {
        float a0, a1;
        unpack2(acc[p], a0, a1);
        op[2 * p]     = a0 * inv;
        op[2 * p + 1] = a1 * inv;
    }
}

// =====================================================================
// Patch attention v8: 1 thread = 1 full query (32 dims). NO shfl.
// Dot = 4 independent depth-4 fma2 chains. K/V rows broadcast from smem
// (16 LDS.128 per key per WARP serving 32 queries). launch_bounds(256,2)
// gives a 128-reg ceiling -> no spills (~95 live regs). 196 queries/block.
// =====================================================================
#define TQA 196
#define TKA 112

__global__ __launch_bounds__(256, 2) void attn_kernel(const float* __restrict__ gating)
{
    __shared__ __align__(16) float Ks[TKA][HDIM];
    __shared__ __align__(16) float Vs[TKA][HDIM];

    const int t = threadIdx.x;
    const int h = blockIdx.y;
    const int b = blockIdx.z;
    const int n = blockIdx.x * TQA + t;
    const bool active = (t < TQA) && (n < NPATCH);
    const int nc = active ? n : (b * 0);   // clamp idle threads to query 0

    const float LOG2E = 1.4426950408889634f;
    const float sl = 0.28867513459481287f * LOG2E;  // heads^-0.5 * log2(e)

    // full 32-dim query, pre-scaled into log2 domain
    ull q2[16];
    {
        const float* qp = g_Q + ((size_t)(b * NPATCH + nc) * EDIM) + h * HDIM;
#pragma unroll
        for (int p = 0; p < 16; p++)
            q2[p] = pack2(qp[2 * p] * sl, qp[2 * p + 1] * sl);
    }

    ull acc[16];
#pragma unroll
    for (int p = 0; p < 16; p++) acc[p] = 0ull;
    float ZP = 0.f;
    const ull ONE2  = pack2(1.f, 1.f);
    const ull ZERO2 = 0ull;

    for (int m0 = 0; m0 < NPATCH; m0 += TKA) {
        __syncthreads();
#pragma unroll
        for (int i = 0; i < 4; i++) {
            const int l = t + i * 256;
            if (l < TKA * 8) {
                const int r  = l >> 3;
                const int cc = (l & 7) << 2;
                const size_t base = ((size_t)(b * NPATCH + m0 + r) * EDIM) + h * HDIM + cc;
                *(float4*)&Ks[r][cc] = *(const float4*)(g_K + base);
                *(float4*)&Vs[r][cc] = *(const float4*)(g_V + base);
            }
        }
        __syncthreads();

        for (int km = 0; km < TKA; ++km) {
            const ulonglong2* kp = (const ulonglong2*)&Ks[km][0];
            // 4 independent chains, depth 4 each
            ull c0 = ZERO2, c1 = ZERO2, c2 = ZERO2, c3 = ZERO2;
            {
                ulonglong2 ka = kp[0], kb = kp[1];
                c0 = fma2(q2[0], ka.x, c0); c1 = fma2(q2[1], ka.y, c1);
                c2 = fma2(q2[2], kb.x, c2); c3 = fma2(q2[3], kb.y, c3);
            }
            {
                ulonglong2 ka = kp[2], kb = kp[3];
                c0 = fma2(q2[4], ka.x, c0); c1 = fma2(q2[5], ka.y, c1);
                c2 = fma2(q2[6], kb.x, c2); c3 = fma2(q2[7], kb.y, c3);
            }
            {
                ulonglong2 ka = kp[4], kb = kp[5];
                c0 = fma2(q2[8],  ka.x, c0); c1 = fma2(q2[9],  ka.y, c1);
                c2 = fma2(q2[10], kb.x, c2); c3 = fma2(q2[11], kb.y, c3);
            }
            {
                ulonglong2 ka = kp[6], kb = kp[7];
                c0 = fma2(q2[12], ka.x, c0); c1 = fma2(q2[13], ka.y, c1);
                c2 = fma2(q2[14], kb.x, c2); c3 = fma2(q2[15], kb.y, c3);
            }
            ull s01 = fma2(c0, ONE2, c1);
            ull s23 = fma2(c2, ONE2, c3);
            ull sA  = fma2(s01, ONE2, s23);
            float s0, s1;
            unpack2(sA, s0, s1);
            const float s = s0 + s1;           // full 32-dim dot, log2 domain

            const float wP = ex2f(s);
            ZP += wP;
            const ull wp2 = pack2(wP, wP);

            const ulonglong2* vp = (const ulonglong2*)&Vs[km][0];
#pragma unroll
            for (int i = 0; i < 8; i++) {
                ulonglong2 vv = vp[i];
                acc[2 * i]     = fma2(wp2, vv.x, acc[2 * i]);
                acc[2 * i + 1] = fma2(wp2, vv.y, acc[2 * i + 1]);
            }
        }
    }

    const float g  = gating[h];
    const float sg = 1.f / (1.f + __expf(-g));
    const float cP = (1.f - sg) / ZP;

    if (active) {
        const float2* pp = (const float2*)(g_posO + (((size_t)(b * NHEAD + h) * NPATCH + n) * HDIM));
        float2* op = (float2*)(g_O + ((size_t)(b * NPATCH + n) * EDIM) + h * HDIM);
#pragma unroll
        for (int p = 0; p < 16; p++) {
            float a0, a1;
            unpack2(acc[p], a0, a1);
            const float2 ps = pp[p];
            float2 o;
            o.x = fmaf(cP, a0, sg * ps.x);
            o.y = fmaf(cP, a1, sg * ps.y);
            op[p] = o;
        }
    }
}

// =====================================================================
extern "C" void kernel_launch(void* const* d_in, const int* in_sizes, int n_in,
                              void* d_out, int out_size)
{
    const float* x   = (const float*)d_in[0];
    const float* Wq  = (const float*)d_in[1];
    const float* Wk  = (const float*)d_in[2];
    const float* Wv  = (const float*)d_in[3];
    const float* Wp  = (const float*)d_in[4];
    const float* bp  = (const float*)d_in[5];
    const float* Wo  = (const float*)d_in[6];
    const float* bo  = (const float*)d_in[7];
    const float* gt  = (const float*)d_in[8];
    float* out = (float*)d_out;

    dim3 gq(49, 6, 3);
    qkv_kernel<<<gq, 256>>>(x, Wq, Wk, Wv);

    dim3 gp(7, NHEAD, BATCH);
    pos_kernel<<<gp, 224>>>(Wp, bp);

    dim3 ga((NPATCH + TQA - 1) / TQA, NHEAD, BATCH);  // (4, 12, 8)
    attn_kernel<<<ga, 256>>>(gt);

    dim3 go(49, 6, 1);
    out_kernel<<<go, 256>>>(Wo, bo, out);
}

// round 11
// speedup vs baseline: 1.4012x; 1.4012x over previous
#include <cuda_runtime.h>

#define BATCH   8
#define NPATCH  784
#define EDIM    384
#define NHEAD   12
#define HDIM    32
#define GRID_S  28

typedef unsigned long long ull;

// -------- scratch (no allocations allowed) --------
__device__ float g_Q[BATCH * NPATCH * EDIM];
__device__ float g_K[BATCH * NPATCH * EDIM];
__device__ float g_V[BATCH * NPATCH * EDIM];
__device__ float g_O[BATCH * NPATCH * EDIM];
__device__ float g_posO[BATCH * NHEAD * NPATCH * HDIM];
__device__ float g_T[BATCH * NHEAD * GRID_S * GRID_S * HDIM];   // separable stage-1
__device__ float g_Zx[NHEAD * GRID_S];

// -------- packed f32x2 helpers (sm_103a) --------
__device__ __forceinline__ ull fma2(ull a, ull b, ull c) {
    ull d;
    asm("fma.rn.f32x2 %0, %1, %2, %3;" : "=l"(d) : "l"(a), "l"(b), "l"(c));
    return d;
}
__device__ __forceinline__ ull pack2(float lo, float hi) {
    ull r;
    asm("mov.b64 %0, {%1, %2};" : "=l"(r) : "f"(lo), "f"(hi));
    return r;
}
__device__ __forceinline__ void unpack2(ull v, float& lo, float& hi) {
    asm("mov.b64 {%0, %1}, %2;" : "=f"(lo), "=f"(hi) : "l"(v));
}
__device__ __forceinline__ float ex2f(float x) {
    float y;
    asm("ex2.approx.f32 %0, %1;" : "=f"(y) : "f"(x));
    return y;
}

// =====================================================================
// GEMM (measured ~42.7us/GEMM): Y[M,384] = X[M,384] @ W^T
// =====================================================================
#define GTK 16

template <bool HAS_BIAS>
__device__ __forceinline__ void gemm_tile(const float* __restrict__ X,
                                          const float* __restrict__ W,
                                          const float* __restrict__ bias,
                                          float* __restrict__ Y)
{
    __shared__ __align__(16) float As[GTK][128];
    __shared__ __align__(16) float Bs[GTK][64];

    const int t    = threadIdx.x;
    const int row0 = blockIdx.x * 128;
    const int col0 = blockIdx.y * 64;
    const int tr   = t >> 4;
    const int tc   = t & 15;

    const int arow = t >> 2;
    const int aj4  = (t & 3) << 2;
    const float* ap0 = X + (size_t)(row0 + arow) * EDIM + aj4;
    const float* ap1 = X + (size_t)(row0 + 64 + arow) * EDIM + aj4;
    const float* bp_ = W + (size_t)(col0 + arow) * EDIM + aj4;

    ull c[8][2];
#pragma unroll
    for (int r = 0; r < 8; r++) { c[r][0] = 0ull; c[r][1] = 0ull; }

    float4 ra0 = *(const float4*)(ap0);
    float4 ra1 = *(const float4*)(ap1);
    float4 rb  = *(const float4*)(bp_);

    for (int s = 0; s < EDIM / GTK; s++) {
        __syncthreads();
        As[aj4 + 0][arow] = ra0.x; As[aj4 + 1][arow] = ra0.y;
        As[aj4 + 2][arow] = ra0.z; As[aj4 + 3][arow] = ra0.w;
        As[aj4 + 0][64 + arow] = ra1.x; As[aj4 + 1][64 + arow] = ra1.y;
        As[aj4 + 2][64 + arow] = ra1.z; As[aj4 + 3][64 + arow] = ra1.w;
        Bs[aj4 + 0][arow] = rb.x; Bs[aj4 + 1][arow] = rb.y;
        Bs[aj4 + 2][arow] = rb.z; Bs[aj4 + 3][arow] = rb.w;
        __syncthreads();

        if (s + 1 < EDIM / GTK) {
            const int ko = (s + 1) * GTK;
            ra0 = *(const float4*)(ap0 + ko);
            ra1 = *(const float4*)(ap1 + ko);
            rb  = *(const float4*)(bp_ + ko);
        }

#pragma unroll
        for (int kk = 0; kk < GTK; kk++) {
            float4 a0 = *(const float4*)&As[kk][tr * 8];
            float4 a1 = *(const float4*)&As[kk][tr * 8 + 4];
            ulonglong2 bb = *(const ulonglong2*)&Bs[kk][tc * 4];
            ull A0 = pack2(a0.x, a0.x);
            ull A1 = pack2(a0.y, a0.y);
            ull A2 = pack2(a0.z, a0.z);
            ull A3 = pack2(a0.w, a0.w);
            ull A4 = pack2(a1.x, a1.x);
            ull A5 = pack2(a1.y, a1.y);
            ull A6 = pack2(a1.z, a1.z);
            ull A7 = pack2(a1.w, a1.w);
            c[0][0] = fma2(A0, bb.x, c[0][0]); c[0][1] = fma2(A0, bb.y, c[0][1]);
            c[1][0] = fma2(A1, bb.x, c[1][0]); c[1][1] = fma2(A1, bb.y, c[1][1]);
            c[2][0] = fma2(A2, bb.x, c[2][0]); c[2][1] = fma2(A2, bb.y, c[2][1]);
            c[3][0] = fma2(A3, bb.x, c[3][0]); c[3][1] = fma2(A3, bb.y, c[3][1]);
            c[4][0] = fma2(A4, bb.x, c[4][0]); c[4][1] = fma2(A4, bb.y, c[4][1]);
            c[5][0] = fma2(A5, bb.x, c[5][0]); c[5][1] = fma2(A5, bb.y, c[5][1]);
            c[6][0] = fma2(A6, bb.x, c[6][0]); c[6][1] = fma2(A6, bb.y, c[6][1]);
            c[7][0] = fma2(A7, bb.x, c[7][0]); c[7][1] = fma2(A7, bb.y, c[7][1]);
        }
    }

    const int j0 = col0 + tc * 4;
    float b0 = 0.f, b1 = 0.f, b2 = 0.f, b3 = 0.f;
    if (HAS_BIAS) {
        float4 bb = *(const float4*)(bias + j0);
        b0 = bb.x; b1 = bb.y; b2 = bb.z; b3 = bb.w;
    }
#pragma unroll
    for (int r = 0; r < 8; r++) {
        const int row = row0 + tr * 8 + r;
        float o0, o1, o2, o3;
        unpack2(c[r][0], o0, o1);
        unpack2(c[r][1], o2, o3);
        float4 o = make_float4(o0 + b0, o1 + b1, o2 + b2, o3 + b3);
        *(float4*)(Y + (size_t)row * EDIM + j0) = o;
    }
}

__global__ __launch_bounds__(256, 3) void qkv_kernel(const float* __restrict__ X,
                                                     const float* __restrict__ Wq,
                                                     const float* __restrict__ Wk,
                                                     const float* __restrict__ Wv)
{
    const float* W;
    float* Y;
    if (blockIdx.z == 0)      { W = Wq; Y = g_Q; }
    else if (blockIdx.z == 1) { W = Wk; Y = g_K; }
    else                      { W = Wv; Y = g_V; }
    gemm_tile<false>(X, W, nullptr, Y);
}

__global__ __launch_bounds__(256, 3) void out_kernel(const float* __restrict__ Wo,
                                                     const float* __restrict__ bo,
                                                     float* __restrict__ Y)
{
    gemm_tile<true>(g_O, Wo, bo, Y);
}

// =====================================================================
// Separable positional softmax (EXACT):
//   logit(n,m) = lx(qx,mx) + ly(qy,my),  lx = w0*dx + w2*dx^2,
//   ly = w1*dy + w2*dy^2 + bp.  weight = fx*fy, Z = Zx*Zy.
// Stage 1: T[b,h,qx,my,:] = sum_mx fx[qx,mx] * V[b,(my,mx),h,:]
// Stage 2: posO[b,h,(qy,qx),:] = sum_my fy[qy,my]*T / (Zx[qx]*Zy[qy])
// Per-row max subtraction for robustness (cancels in the ratio).
// =====================================================================
__global__ __launch_bounds__(256) void pos1_kernel(const float* __restrict__ Wpos)
{
    __shared__ float Vs[GRID_S][HDIM];
    __shared__ float fx[GRID_S][GRID_S];
    __shared__ float Zx[GRID_S];

    const int t  = threadIdx.x;
    const int my = blockIdx.x;
    const int h  = blockIdx.y;
    const int b  = blockIdx.z;
    const float LOG2E = 1.4426950408889634f;
    const float w0 = Wpos[h * 3 + 0];
    const float w2 = Wpos[h * 3 + 2];

    for (int i = t; i < GRID_S * HDIM; i += 256) {
        const int mx = i >> 5, d = i & 31;
        Vs[mx][d] = g_V[((size_t)(b * NPATCH + my * GRID_S + mx) * EDIM) + h * HDIM + d];
    }
    for (int i = t; i < GRID_S * GRID_S; i += 256) {
        const int qx = i / GRID_S, mx = i % GRID_S;
        const float dx = (float)(mx - qx);
        fx[qx][mx] = fmaf(w2, dx * dx, w0 * dx);   // logit, exp'd below
    }
    __syncthreads();
    if (t < GRID_S) {
        float mmax = -1e30f;
#pragma unroll
        for (int mx = 0; mx < GRID_S; mx++) mmax = fmaxf(mmax, fx[t][mx]);
        float z = 0.f;
#pragma unroll
        for (int mx = 0; mx < GRID_S; mx++) {
            const float f = ex2f((fx[t][mx] - mmax) * LOG2E);
            fx[t][mx] = f;
            z += f;
        }
        Zx[t] = z;
        g_Zx[h * GRID_S + t] = z;    // benign race: identical value from every b
    }
    __syncthreads();

    float* Tp = g_T + ((((size_t)(b * NHEAD + h) * GRID_S) * GRID_S) * HDIM);
    for (int i = t; i < GRID_S * HDIM; i += 256) {
        const int qx = i >> 5, d = i & 31;
        float s = 0.f;
#pragma unroll
        for (int mx = 0; mx < GRID_S; mx++) s = fmaf(fx[qx][mx], Vs[mx][d], s);
        Tp[((size_t)qx * GRID_S + my) * HDIM + d] = s;
    }
}

__global__ __launch_bounds__(256) void pos2_kernel(const float* __restrict__ Wpos,
                                                   const float* __restrict__ bpos)
{
    __shared__ float Ts[GRID_S][HDIM];
    __shared__ float fy[GRID_S][GRID_S];
    __shared__ float Zy[GRID_S];

    const int t  = threadIdx.x;
    const int qx = blockIdx.x;
    const int h  = blockIdx.y;
    const int b  = blockIdx.z;
    const float LOG2E = 1.4426950408889634f;
    const float w1 = Wpos[h * 3 + 1];
    const float w2 = Wpos[h * 3 + 2];
    const float bp = bpos[h];

    const float* Tp = g_T + ((((size_t)(b * NHEAD + h) * GRID_S + qx) * GRID_S) * HDIM);
    for (int i = t; i < GRID_S * HDIM; i += 256) {
        Ts[i >> 5][i & 31] = Tp[i];
    }
    for (int i = t; i < GRID_S * GRID_S; i += 256) {
        const int qy = i / GRID_S, my = i % GRID_S;
        const float dy = (float)(my - qy);
        fy[qy][my] = fmaf(w2, dy * dy, w1 * dy) + bp;
    }
    __syncthreads();
    if (t < GRID_S) {
        float mmax = -1e30f;
#pragma unroll
        for (int my = 0; my < GRID_S; my++) mmax = fmaxf(mmax, fy[t][my]);
        float z = 0.f;
#pragma unroll
        for (int my = 0; my < GRID_S; my++) {
            const float f = ex2f((fy[t][my] - mmax) * LOG2E);
            fy[t][my] = f;
            z += f;
        }
        Zy[t] = z;
    }
    __syncthreads();

    const float zx = g_Zx[h * GRID_S + qx];
    for (int i = t; i < GRID_S * HDIM; i += 256) {
        const int qy = i >> 5, d = i & 31;
        float s = 0.f;
#pragma unroll
        for (int my = 0; my < GRID_S; my++) s = fmaf(fy[qy][my], Ts[my][d], s);
        const int n = qy * GRID_S + qx;
        g_posO[(((size_t)(b * NHEAD + h) * NPATCH + n) * HDIM) + d] = s / (zx * Zy[qy]);
    }
}

// =====================================================================
// Patch attention v9: 2 threads/query, 2 keys per iteration (software
// pipeline: both dots issue before the softmax serial section; V rows
// preload under the shfl+ex2 shadow; K registers die before V is born).
// launch_bounds(256,3) -> 6 warps/SMSP, ~70 live regs (no spills).
// =====================================================================
#define TQ 128
#define TK 112

__global__ __launch_bounds__(256, 3) void attn_kernel(const float* __restrict__ gating)
{
    __shared__ __align__(16) float Ks[TK][HDIM];
    __shared__ __align__(16) float Vs[TK][HDIM];

    const int t    = threadIdx.x;
    const int qi   = t >> 1;
    const int half = t & 1;
    const int h = blockIdx.y;
    const int b = blockIdx.z;
    const int n = blockIdx.x * TQ + qi;
    const bool active = (n < NPATCH);
    const int nc = active ? n : (NPATCH - 1);

    const float LOG2E = 1.4426950408889634f;
    const float sl = 0.28867513459481287f * LOG2E;  // heads^-0.5 * log2(e)

    ull q2[8];
    {
        const float* qp = g_Q + ((size_t)(b * NPATCH + nc) * EDIM) + h * HDIM + half * 16;
#pragma unroll
        for (int p = 0; p < 8; p++)
            q2[p] = pack2(qp[2 * p] * sl, qp[2 * p + 1] * sl);
    }

    ull accP[8];
#pragma unroll
    for (int p = 0; p < 8; p++) accP[p] = 0ull;
    float ZP0 = 0.f, ZP1 = 0.f;
    const ull ONE2  = pack2(1.f, 1.f);
    const ull ZERO2 = 0ull;

    for (int m0 = 0; m0 < NPATCH; m0 += TK) {
        __syncthreads();
#pragma unroll
        for (int i = 0; i < 4; i++) {
            const int l = t + i * 256;
            if (l < TK * 8) {
                const int r  = l >> 3;
                const int cc = (l & 7) << 2;
                const size_t base = ((size_t)(b * NPATCH + m0 + r) * EDIM) + h * HDIM + cc;
                *(float4*)&Ks[r][cc] = *(const float4*)(g_K + base);
                *(float4*)&Vs[r][cc] = *(const float4*)(g_V + base);
            }
        }
        __syncthreads();

        for (int km = 0; km < TK; km += 2) {
            ull dS0, dS1;
            {   // K scope: registers die before V loads
                const ulonglong2* kp0 = (const ulonglong2*)&Ks[km][half * 16];
                const ulonglong2* kp1 = (const ulonglong2*)&Ks[km + 1][half * 16];
                ulonglong2 k0a = kp0[0], k0b = kp0[1], k0c = kp0[2], k0d = kp0[3];
                ulonglong2 k1a = kp1[0], k1b = kp1[1], k1c = kp1[2], k1d = kp1[3];
                ull dA0 = fma2(q2[0], k0a.x, ZERO2);
                ull dB0 = fma2(q2[4], k0c.x, ZERO2);
                ull dA1 = fma2(q2[0], k1a.x, ZERO2);
                ull dB1 = fma2(q2[4], k1c.x, ZERO2);
                dA0 = fma2(q2[1], k0a.y, dA0);  dB0 = fma2(q2[5], k0c.y, dB0);
                dA1 = fma2(q2[1], k1a.y, dA1);  dB1 = fma2(q2[5], k1c.y, dB1);
                dA0 = fma2(q2[2], k0b.x, dA0);  dB0 = fma2(q2[6], k0d.x, dB0);
                dA1 = fma2(q2[2], k1b.x, dA1);  dB1 = fma2(q2[6], k1d.x, dB1);
                dA0 = fma2(q2[3], k0b.y, dA0);  dB0 = fma2(q2[7], k0d.y, dB0);
                dA1 = fma2(q2[3], k1b.y, dA1);  dB1 = fma2(q2[7], k1d.y, dB1);
                dS0 = fma2(dA0, ONE2, dB0);
                dS1 = fma2(dA1, ONE2, dB1);
            }
            // V preload (consumed after the softmax serial section)
            const ulonglong2* vp0 = (const ulonglong2*)&Vs[km][half * 16];
            const ulonglong2* vp1 = (const ulonglong2*)&Vs[km + 1][half * 16];
            ulonglong2 v0a = vp0[0], v0b = vp0[1], v0c = vp0[2], v0d = vp0[3];
            ulonglong2 v1a = vp1[0], v1b = vp1[1], v1c = vp1[2], v1d = vp1[3];

            float s0a, s0b, s1a, s1b;
            unpack2(dS0, s0a, s0b);
            unpack2(dS1, s1a, s1b);
            float s0 = s0a + s0b;
            float s1 = s1a + s1b;
            s0 += __shfl_xor_sync(0xffffffffu, s0, 1);
            s1 += __shfl_xor_sync(0xffffffffu, s1, 1);

            const float wP0 = ex2f(s0);
            const float wP1 = ex2f(s1);
            ZP0 += wP0;
            ZP1 += wP1;
            const ull wp20 = pack2(wP0, wP0);
            const ull wp21 = pack2(wP1, wP1);

            accP[0] = fma2(wp20, v0a.x, accP[0]);
            accP[1] = fma2(wp20, v0a.y, accP[1]);
            accP[2] = fma2(wp20, v0b.x, accP[2]);
            accP[3] = fma2(wp20, v0b.y, accP[3]);
            accP[4] = fma2(wp20, v0c.x, accP[4]);
            accP[5] = fma2(wp20, v0c.y, accP[5]);
            accP[6] = fma2(wp20, v0d.x, accP[6]);
            accP[7] = fma2(wp20, v0d.y, accP[7]);
            accP[0] = fma2(wp21, v1a.x, accP[0]);
            accP[1] = fma2(wp21, v1a.y, accP[1]);
            accP[2] = fma2(wp21, v1b.x, accP[2]);
            accP[3] = fma2(wp21, v1b.y, accP[3]);
            accP[4] = fma2(wp21, v1c.x, accP[4]);
            accP[5] = fma2(wp21, v1c.y, accP[5]);
            accP[6] = fma2(wp21, v1d.x, accP[6]);
            accP[7] = fma2(wp21, v1d.y, accP[7]);
        }
    }

    const float ZP = ZP0 + ZP1;
    const float g  = gating[h];
    const float sg = 1.f / (1.f + __expf(-g));
    const float cP = (1.f - sg) / ZP;

    if (active) {
        const float2* pp = (const float2*)(g_posO + (((size_t)(b * NHEAD + h) * NPATCH + n) * HDIM) + half * 16);
        float2* op = (float2*)(g_O + ((size_t)(b * NPATCH + n) * EDIM) + h * HDIM + half * 16);
#pragma unroll
        for (int p = 0; p < 8; p++) {
            float p0, p1;
            unpack2(accP[p], p0, p1);
            const float2 ps = pp[p];
            float2 o;
            o.x = fmaf(cP, p0, sg * ps.x);
            o.y = fmaf(cP, p1, sg * ps.y);
            op[p] = o;
        }
    }
}

// =====================================================================
extern "C" void kernel_launch(void* const* d_in, const int* in_sizes, int n_in,
                              void* d_out, int out_size)
{
    const float* x   = (const float*)d_in[0];
    const float* Wq  = (const float*)d_in[1];
    const float* Wk  = (const float*)d_in[2];
    const float* Wv  = (const float*)d_in[3];
    const float* Wp  = (const float*)d_in[4];
    const float* bp  = (const float*)d_in[5];
    const float* Wo  = (const float*)d_in[6];
    const float* bo  = (const float*)d_in[7];
    const float* gt  = (const float*)d_in[8];
    float* out = (float*)d_out;

    dim3 gq(49, 6, 3);
    qkv_kernel<<<gq, 256>>>(x, Wq, Wk, Wv);

    dim3 gp1(GRID_S, NHEAD, BATCH);      // (28, 12, 8)
    pos1_kernel<<<gp1, 256>>>(Wp);
    pos2_kernel<<<gp1, 256>>>(Wp, bp);

    dim3 ga((NPATCH + TQ - 1) / TQ, NHEAD, BATCH);   // (7, 12, 8)
    attn_kernel<<<ga, 256>>>(gt);

    dim3 go(49, 6, 1);
    out_kernel<<<go, 256>>>(Wo, bo, out);
}

// round 13
// speedup vs baseline: 1.7770x; 1.2681x over previous
#include <cuda_runtime.h>
#include <cuda_bf16.h>

#define BATCH   8
#define NPATCH  784
#define EDIM    384
#define NHEAD   12
#define HDIM    32
#define GRID_S  28

#define NX (BATCH * NPATCH * EDIM)   // 2408448
#define NW (EDIM * EDIM)             // 147456

typedef unsigned long long ull;
typedef __nv_bfloat16 bf16;

// -------- scratch (no allocations allowed) --------
__device__ float g_QKV[3 * NX];
#define g_Q (g_QKV)
#define g_K (g_QKV + NX)
#define g_V (g_QKV + 2 * NX)
__device__ float g_O[NX];
__device__ float g_posO[BATCH * NHEAD * NPATCH * HDIM];
__device__ float g_T[BATCH * NHEAD * GRID_S * GRID_S * HDIM];
__device__ float g_Zx[NHEAD * GRID_S];
__device__ bf16 g_Xh[NX];
__device__ bf16 g_Xl[NX];
__device__ bf16 g_Oh[NX];
__device__ bf16 g_Ol[NX];
__device__ bf16 g_Wh[4 * NW];   // Wq, Wk, Wv, Wo
__device__ bf16 g_Wl[4 * NW];

// -------- packed f32x2 helpers (sm_103a) --------
__device__ __forceinline__ ull fma2(ull a, ull b, ull c) {
    ull d;
    asm("fma.rn.f32x2 %0, %1, %2, %3;" : "=l"(d) : "l"(a), "l"(b), "l"(c));
    return d;
}
__device__ __forceinline__ ull pack2(float lo, float hi) {
    ull r;
    asm("mov.b64 %0, {%1, %2};" : "=l"(r) : "f"(lo), "f"(hi));
    return r;
}
__device__ __forceinline__ void unpack2(ull v, float& lo, float& hi) {
    asm("mov.b64 {%0, %1}, %2;" : "=f"(lo), "=f"(hi) : "l"(v));
}
__device__ __forceinline__ float ex2f(float x) {
    float y;
    asm("ex2.approx.f32 %0, %1;" : "=f"(y) : "f"(x));
    return y;
}

// -------- warp-level bf16 MMA (sm_80+ baseline, legal on compute_103) ----
__device__ __forceinline__ void mma_bf16(float* d, const unsigned* a, const unsigned* b) {
    asm volatile(
        "mma.sync.aligned.m16n8k16.row.col.f32.bf16.bf16.f32 "
        "{%0,%1,%2,%3}, {%4,%5,%6,%7}, {%8,%9}, {%0,%1,%2,%3};"
        : "+f"(d[0]), "+f"(d[1]), "+f"(d[2]), "+f"(d[3])
        : "r"(a[0]), "r"(a[1]), "r"(a[2]), "r"(a[3]), "r"(b[0]), "r"(b[1]));
}

// =====================================================================
// Split fp32 -> (bf16 hi, bf16 lo) for tensor-core GEMMs.
// =====================================================================
__global__ __launch_bounds__(256) void split_in_kernel(const float* __restrict__ x,
                                                       const float* __restrict__ Wq,
                                                       const float* __restrict__ Wk,
                                                       const float* __restrict__ Wv,
                                                       const float* __restrict__ Wo)
{
    const int i = blockIdx.x * 256 + threadIdx.x;
    const int total = NX + 4 * NW;
    if (i >= total) return;
    float v;
    bf16 *hp, *lp;
    if (i < NX) {
        v = x[i];
        hp = g_Xh + i; lp = g_Xl + i;
    } else {
        int j = i - NX;
        int w = 0;
        while (j >= NW) { j -= NW; w++; }   // <= 3 iters
        const float* src = (w == 0) ? Wq : (w == 1) ? Wk : (w == 2) ? Wv : Wo;
        v = src[j];
        hp = g_Wh + (i - NX); lp = g_Wl + (i - NX);
    }
    const bf16 h = __float2bfloat16(v);
    const bf16 l = __float2bfloat16(v - __bfloat162float(h));
    *hp = h; *lp = l;
}

__global__ __launch_bounds__(256) void split_o_kernel()
{
    const int i = blockIdx.x * 256 + threadIdx.x;
    if (i >= NX) return;
    const float v = g_O[i];
    const bf16 h = __float2bfloat16(v);
    const bf16 l = __float2bfloat16(v - __bfloat162float(h));
    g_Oh[i] = h; g_Ol[i] = l;
}

// =====================================================================
// bf16-split GEMM on HMMA (mma.sync): Y[6272,384] = A @ B^T (+bias).
// CTA tile 128x64, 8 warps, warp tile 64x16 (4 m16 x 2 n8 frags).
// K = 384 in 6 slabs of 64. 3-term split: Ah*Bh + Ah*Bl + Al*Bh.
// Smem rows padded to 72 bf16 -> conflict-free b32 fragment loads.
// =====================================================================
#define MT 128
#define NT 64
#define KT 64
#define SPAD 72
#define SM_A (MT * SPAD)            // bf16 elements per A buffer
#define SM_B (NT * SPAD)
#define MM_SMEM ((2 * SM_A + 2 * SM_B) * 2)   // bytes = 55296

__device__ __forceinline__ void mm_core(const bf16* __restrict__ Ah,
                                        const bf16* __restrict__ Al,
                                        const bf16* __restrict__ Bh,
                                        const bf16* __restrict__ Bl,
                                        const float* __restrict__ bias,
                                        float* __restrict__ Y)
{
    extern __shared__ __align__(16) unsigned char smraw[];
    bf16* sAh = (bf16*)smraw;
    bf16* sAl = sAh + SM_A;
    bf16* sBh = sAl + SM_A;
    bf16* sBl = sBh + SM_B;

    const int t    = threadIdx.x;
    const int wid  = t >> 5;
    const int lane = t & 31;
    const int gid  = lane >> 2;      // 0..7
    const int tig  = lane & 3;       // 0..3
    const int warp_m = (wid & 1) * 64;
    const int warp_n = (wid >> 1) * 16;
    const int row0 = blockIdx.x * MT;
    const int col0 = blockIdx.y * NT;

    float acc[4][2][4];
#pragma unroll
    for (int i = 0; i < 4; i++)
#pragma unroll
        for (int j = 0; j < 2; j++)
#pragma unroll
            for (int c = 0; c < 4; c++) acc[i][j][c] = 0.f;

    for (int kt = 0; kt < EDIM / KT; kt++) {
        const int kb = kt * KT;
        __syncthreads();
        // A tiles: 128 rows x 64 cols = 1024 uint4 per buffer
#pragma unroll
        for (int i = 0; i < 4; i++) {
            const int idx = t + i * 256;
            const int r = idx >> 3, c = (idx & 7) * 8;
            const size_t g = (size_t)(row0 + r) * EDIM + kb + c;
            *(uint4*)&sAh[r * SPAD + c] = *(const uint4*)&Ah[g];
            *(uint4*)&sAl[r * SPAD + c] = *(const uint4*)&Al[g];
        }
        // B tiles: 64 rows x 64 cols = 512 uint4 per buffer
#pragma unroll
        for (int i = 0; i < 2; i++) {
            const int idx = t + i * 256;
            const int r = idx >> 3, c = (idx & 7) * 8;
            const size_t g = (size_t)(col0 + r) * EDIM + kb + c;
            *(uint4*)&sBh[r * SPAD + c] = *(const uint4*)&Bh[g];
            *(uint4*)&sBl[r * SPAD + c] = *(const uint4*)&Bl[g];
        }
        __syncthreads();

#pragma unroll
        for (int ks = 0; ks < KT / 16; ks++) {
            const int c0 = ks * 16 + tig * 2;
            const int c1 = c0 + 8;
            unsigned ah[4][4], al[4][4];
#pragma unroll
            for (int i = 0; i < 4; i++) {
                const int r0 = (warp_m + i * 16 + gid) * SPAD;
                const int r1 = r0 + 8 * SPAD;
                ah[i][0] = *(const unsigned*)&sAh[r0 + c0];
                ah[i][1] = *(const unsigned*)&sAh[r1 + c0];
                ah[i][2] = *(const unsigned*)&sAh[r0 + c1];
                ah[i][3] = *(const unsigned*)&sAh[r1 + c1];
                al[i][0] = *(const unsigned*)&sAl[r0 + c0];
                al[i][1] = *(const unsigned*)&sAl[r1 + c0];
                al[i][2] = *(const unsigned*)&sAl[r0 + c1];
                al[i][3] = *(const unsigned*)&sAl[r1 + c1];
            }
            unsigned bh[2][2], bl[2][2];
#pragma unroll
            for (int j = 0; j < 2; j++) {
                const int nr = (warp_n + j * 8 + gid) * SPAD;
                bh[j][0] = *(const unsigned*)&sBh[nr + c0];
                bh[j][1] = *(const unsigned*)&sBh[nr + c1];
                bl[j][0] = *(const unsigned*)&sBl[nr + c0];
                bl[j][1] = *(const unsigned*)&sBl[nr + c1];
            }
#pragma unroll
            for (int i = 0; i < 4; i++) {
#pragma unroll
                for (int j = 0; j < 2; j++) {
                    mma_bf16(acc[i][j], ah[i], bh[j]);
                    mma_bf16(acc[i][j], ah[i], bl[j]);
                    mma_bf16(acc[i][j], al[i], bh[j]);
                }
            }
        }
    }

    // epilogue: c0,c1 -> (row, col..col+1); c2,c3 -> (row+8, ...)
#pragma unroll
    for (int i = 0; i < 4; i++) {
        const int row = row0 + warp_m + i * 16 + gid;
#pragma unroll
        for (int j = 0; j < 2; j++) {
            const int col = col0 + warp_n + j * 8 + tig * 2;
            float b0 = 0.f, b1 = 0.f;
            if (bias) { b0 = bias[col]; b1 = bias[col + 1]; }
            float2 o01 = make_float2(acc[i][j][0] + b0, acc[i][j][1] + b1);
            float2 o23 = make_float2(acc[i][j][2] + b0, acc[i][j][3] + b1);
            *(float2*)(Y + (size_t)row * EDIM + col)       = o01;
            *(float2*)(Y + (size_t)(row + 8) * EDIM + col) = o23;
        }
    }
}

__global__ __launch_bounds__(256) void qkv_mm_kernel()
{
    const int z = blockIdx.z;
    mm_core(g_Xh, g_Xl, g_Wh + (size_t)z * NW, g_Wl + (size_t)z * NW,
            nullptr, g_QKV + (size_t)z * NX);
}

__global__ __launch_bounds__(256) void out_mm_kernel(const float* __restrict__ bo,
                                                     float* __restrict__ Y)
{
    mm_core(g_Oh, g_Ol, g_Wh + 3 * (size_t)NW, g_Wl + 3 * (size_t)NW, bo, Y);
}

// =====================================================================
// Separable positional softmax (EXACT) — unchanged from R11.
// =====================================================================
__global__ __launch_bounds__(256) void pos1_kernel(const float* __restrict__ Wpos)
{
    __shared__ float Vs[GRID_S][HDIM];
    __shared__ float fx[GRID_S][GRID_S];
    __shared__ float Zx[GRID_S];

    const int t  = threadIdx.x;
    const int my = blockIdx.x;
    const int h  = blockIdx.y;
    const int b  = blockIdx.z;
    const float LOG2E = 1.4426950408889634f;
    const float w0 = Wpos[h * 3 + 0];
    const float w2 = Wpos[h * 3 + 2];

    for (int i = t; i < GRID_S * HDIM; i += 256) {
        const int mx = i >> 5, d = i & 31;
        Vs[mx][d] = g_V[((size_t)(b * NPATCH + my * GRID_S + mx) * EDIM) + h * HDIM + d];
    }
    for (int i = t; i < GRID_S * GRID_S; i += 256) {
        const int qx = i / GRID_S, mx = i % GRID_S;
        const float dx = (float)(mx - qx);
        fx[qx][mx] = fmaf(w2, dx * dx, w0 * dx);
    }
    __syncthreads();
    if (t < GRID_S) {
        float mmax = -1e30f;
#pragma unroll
        for (int mx = 0; mx < GRID_S; mx++) mmax = fmaxf(mmax, fx[t][mx]);
        float z = 0.f;
#pragma unroll
        for (int mx = 0; mx < GRID_S; mx++) {
            const float f = ex2f((fx[t][mx] - mmax) * LOG2E);
            fx[t][mx] = f;
            z += f;
        }
        Zx[t] = z;
        g_Zx[h * GRID_S + t] = z;    // benign race: identical value from every b
    }
    __syncthreads();

    float* Tp = g_T + ((((size_t)(b * NHEAD + h) * GRID_S) * GRID_S) * HDIM);
    for (int i = t; i < GRID_S * HDIM; i += 256) {
        const int qx = i >> 5, d = i & 31;
        float s = 0.f;
#pragma unroll
        for (int mx = 0; mx < GRID_S; mx++) s = fmaf(fx[qx][mx], Vs[mx][d], s);
        Tp[((size_t)qx * GRID_S + my) * HDIM + d] = s;
    }
}

__global__ __launch_bounds__(256) void pos2_kernel(const float* __restrict__ Wpos,
                                                   const float* __restrict__ bpos)
{
    __shared__ float Ts[GRID_S][HDIM];
    __shared__ float fy[GRID_S][GRID_S];
    __shared__ float Zy[GRID_S];

    const int t  = threadIdx.x;
    const int qx = blockIdx.x;
    const int h  = blockIdx.y;
    const int b  = blockIdx.z;
    const float LOG2E = 1.4426950408889634f;
    const float w1 = Wpos[h * 3 + 1];
    const float w2 = Wpos[h * 3 + 2];
    const float bp = bpos[h];

    const float* Tp = g_T + ((((size_t)(b * NHEAD + h) * GRID_S + qx) * GRID_S) * HDIM);
    for (int i = t; i < GRID_S * HDIM; i += 256) {
        Ts[i >> 5][i & 31] = Tp[i];
    }
    for (int i = t; i < GRID_S * GRID_S; i += 256) {
        const int qy = i / GRID_S, my = i % GRID_S;
        const float dy = (float)(my - qy);
        fy[qy][my] = fmaf(w2, dy * dy, w1 * dy) + bp;
    }
    __syncthreads();
    if (t < GRID_S) {
        float mmax = -1e30f;
#pragma unroll
        for (int my = 0; my < GRID_S; my++) mmax = fmaxf(mmax, fy[t][my]);
        float z = 0.f;
#pragma unroll
        for (int my = 0; my < GRID_S; my++) {
            const float f = ex2f((fy[t][my] - mmax) * LOG2E);
            fy[t][my] = f;
            z += f;
        }
        Zy[t] = z;
    }
    __syncthreads();

    const float zx = g_Zx[h * GRID_S + qx];
    for (int i = t; i < GRID_S * HDIM; i += 256) {
        const int qy = i >> 5, d = i & 31;
        float s = 0.f;
#pragma unroll
        for (int my = 0; my < GRID_S; my++) s = fmaf(fy[qy][my], Ts[my][d], s);
        const int n = qy * GRID_S + qx;
        g_posO[(((size_t)(b * NHEAD + h) * NPATCH + n) * HDIM) + d] = s / (zx * Zy[qy]);
    }
}

// =====================================================================
// Patch attention — unchanged from R11 (2 threads/query, 2-key pipeline).
// =====================================================================
#define TQ 128
#define TK 112

__global__ __launch_bounds__(256, 3) void attn_kernel(const float* __restrict__ gating)
{
    __shared__ __align__(16) float Ks[TK][HDIM];
    __shared__ __align__(16) float Vs[TK][HDIM];

    const int t    = threadIdx.x;
    const int qi   = t >> 1;
    const int half = t & 1;
    const int h = blockIdx.y;
    const int b = blockIdx.z;
    const int n = blockIdx.x * TQ + qi;
    const bool active = (n < NPATCH);
    const int nc = active ? n : (NPATCH - 1);

    const float LOG2E = 1.4426950408889634f;
    const float sl = 0.28867513459481287f * LOG2E;

    ull q2[8];
    {
        const float* qp = g_Q + ((size_t)(b * NPATCH + nc) * EDIM) + h * HDIM + half * 16;
#pragma unroll
        for (int p = 0; p < 8; p++)
            q2[p] = pack2(qp[2 * p] * sl, qp[2 * p + 1] * sl);
    }

    ull accP[8];
#pragma unroll
    for (int p = 0; p < 8; p++) accP[p] = 0ull;
    float ZP0 = 0.f, ZP1 = 0.f;
    const ull ONE2  = pack2(1.f, 1.f);
    const ull ZERO2 = 0ull;

    for (int m0 = 0; m0 < NPATCH; m0 += TK) {
        __syncthreads();
#pragma unroll
        for (int i = 0; i < 4; i++) {
            const int l = t + i * 256;
            if (l < TK * 8) {
                const int r  = l >> 3;
                const int cc = (l & 7) << 2;
                const size_t base = ((size_t)(b * NPATCH + m0 + r) * EDIM) + h * HDIM + cc;
                *(float4*)&Ks[r][cc] = *(const float4*)(g_K + base);
                *(float4*)&Vs[r][cc] = *(const float4*)(g_V + base);
            }
        }
        __syncthreads();

        for (int km = 0; km < TK; km += 2) {
            ull dS0, dS1;
            {
                const ulonglong2* kp0 = (const ulonglong2*)&Ks[km][half * 16];
                const ulonglong2* kp1 = (const ulonglong2*)&Ks[km + 1][half * 16];
                ulonglong2 k0a = kp0[0], k0b = kp0[1], k0c = kp0[2], k0d = kp0[3];
                ulonglong2 k1a = kp1[0], k1b = kp1[1], k1c = kp1[2], k1d = kp1[3];
                ull dA0 = fma2(q2[0], k0a.x, ZERO2);
                ull dB0 = fma2(q2[4], k0c.x, ZERO2);
                ull dA1 = fma2(q2[0], k1a.x, ZERO2);
                ull dB1 = fma2(q2[4], k1c.x, ZERO2);
                dA0 = fma2(q2[1], k0a.y, dA0);  dB0 = fma2(q2[5], k0c.y, dB0);
                dA1 = fma2(q2[1], k1a.y, dA1);  dB1 = fma2(q2[5], k1c.y, dB1);
                dA0 = fma2(q2[2], k0b.x, dA0);  dB0 = fma2(q2[6], k0d.x, dB0);
                dA1 = fma2(q2[2], k1b.x, dA1);  dB1 = fma2(q2[6], k1d.x, dB1);
                dA0 = fma2(q2[3], k0b.y, dA0);  dB0 = fma2(q2[7], k0d.y, dB0);
                dA1 = fma2(q2[3], k1b.y, dA1);  dB1 = fma2(q2[7], k1d.y, dB1);
                dS0 = fma2(dA0, ONE2, dB0);
                dS1 = fma2(dA1, ONE2, dB1);
            }
            const ulonglong2* vp0 = (const ulonglong2*)&Vs[km][half * 16];
            const ulonglong2* vp1 = (const ulonglong2*)&Vs[km + 1][half * 16];
            ulonglong2 v0a = vp0[0], v0b = vp0[1], v0c = vp0[2], v0d = vp0[3];
            ulonglong2 v1a = vp1[0], v1b = vp1[1], v1c = vp1[2], v1d = vp1[3];

            float s0a, s0b, s1a, s1b;
            unpack2(dS0, s0a, s0b);
            unpack2(dS1, s1a, s1b);
            float s0 = s0a + s0b;
            float s1 = s1a + s1b;
            s0 += __shfl_xor_sync(0xffffffffu, s0, 1);
            s1 += __shfl_xor_sync(0xffffffffu, s1, 1);

            const float wP0 = ex2f(s0);
            const float wP1 = ex2f(s1);
            ZP0 += wP0;
            ZP1 += wP1;
            const ull wp20 = pack2(wP0, wP0);
            const ull wp21 = pack2(wP1, wP1);

            accP[0] = fma2(wp20, v0a.x, accP[0]);
            accP[1] = fma2(wp20, v0a.y, accP[1]);
            accP[2] = fma2(wp20, v0b.x, accP[2]);
            accP[3] = fma2(wp20, v0b.y, accP[3]);
            accP[4] = fma2(wp20, v0c.x, accP[4]);
            accP[5] = fma2(wp20, v0c.y, accP[5]);
            accP[6] = fma2(wp20, v0d.x, accP[6]);
            accP[7] = fma2(wp20, v0d.y, accP[7]);
            accP[0] = fma2(wp21, v1a.x, accP[0]);
            accP[1] = fma2(wp21, v1a.y, accP[1]);
            accP[2] = fma2(wp21, v1b.x, accP[2]);
            accP[3] = fma2(wp21, v1b.y, accP[3]);
            accP[4] = fma2(wp21, v1c.x, accP[4]);
            accP[5] = fma2(wp21, v1c.y, accP[5]);
            accP[6] = fma2(wp21, v1d.x, accP[6]);
            accP[7] = fma2(wp21, v1d.y, accP[7]);
        }
    }

    const float ZP = ZP0 + ZP1;
    const float g  = gating[h];
    const float sg = 1.f / (1.f + __expf(-g));
    const float cP = (1.f - sg) / ZP;

    if (active) {
        const float2* pp = (const float2*)(g_posO + (((size_t)(b * NHEAD + h) * NPATCH + n) * HDIM) + half * 16);
        float2* op = (float2*)(g_O + ((size_t)(b * NPATCH + n) * EDIM) + h * HDIM + half * 16);
#pragma unroll
        for (int p = 0; p < 8; p++) {
            float p0, p1;
            unpack2(accP[p], p0, p1);
            const float2 ps = pp[p];
            float2 o;
            o.x = fmaf(cP, p0, sg * ps.x);
            o.y = fmaf(cP, p1, sg * ps.y);
            op[p] = o;
        }
    }
}

// =====================================================================
extern "C" void kernel_launch(void* const* d_in, const int* in_sizes, int n_in,
                              void* d_out, int out_size)
{
    const float* x   = (const float*)d_in[0];
    const float* Wq  = (const float*)d_in[1];
    const float* Wk  = (const float*)d_in[2];
    const float* Wv  = (const float*)d_in[3];
    const float* Wp  = (const float*)d_in[4];
    const float* bp  = (const float*)d_in[5];
    const float* Wo  = (const float*)d_in[6];
    const float* bo  = (const float*)d_in[7];
    const float* gt  = (const float*)d_in[8];
    float* out = (float*)d_out;

    cudaFuncSetAttribute(qkv_mm_kernel, cudaFuncAttributeMaxDynamicSharedMemorySize, MM_SMEM);
    cudaFuncSetAttribute(out_mm_kernel, cudaFuncAttributeMaxDynamicSharedMemorySize, MM_SMEM);

    // 1. split x + weights to bf16 hi/lo
    split_in_kernel<<<(NX + 4 * NW + 255) / 256, 256>>>(x, Wq, Wk, Wv, Wo);

    // 2. Q,K,V projections on HMMA
    dim3 gq(49, 6, 3);
    qkv_mm_kernel<<<gq, 256, MM_SMEM>>>();

    // 3. positional softmax (separable, exact)
    dim3 gp1(GRID_S, NHEAD, BATCH);
    pos1_kernel<<<gp1, 256>>>(Wp);
    pos2_kernel<<<gp1, 256>>>(Wp, bp);

    // 4. patch attention + gated blend
    dim3 ga((NPATCH + TQ - 1) / TQ, NHEAD, BATCH);
    attn_kernel<<<ga, 256>>>(gt);

    // 5. split O, output projection on HMMA
    split_o_kernel<<<(NX + 255) / 256, 256>>>();
    dim3 go(49, 6, 1);
    out_mm_kernel<<<go, 256, MM_SMEM>>>(bo, out);
}

// round 14
// speedup vs baseline: 2.6802x; 1.5083x over previous
#include <cuda_runtime.h>
#include <cuda_bf16.h>

#define BATCH   8
#define NPATCH  784
#define EDIM    384
#define NHEAD   12
#define HDIM    32
#define GRID_S  28

#define NX (BATCH * NPATCH * EDIM)   // 2408448
#define NW (EDIM * EDIM)             // 147456

typedef unsigned long long ull;
typedef __nv_bfloat16 bf16;

// -------- scratch (no allocations allowed) --------
__device__ float g_V[NX];                              // f32 V (pos kernels)
__device__ float g_posO[BATCH * NHEAD * NPATCH * HDIM];
__device__ float g_T[BATCH * NHEAD * GRID_S * GRID_S * HDIM];
__device__ float g_Zx[NHEAD * GRID_S];
__device__ bf16 g_Qh[NX], g_Ql[NX];
__device__ bf16 g_Kh[NX], g_Kl[NX];
__device__ bf16 g_Vh[NX], g_Vl[NX];
__device__ bf16 g_Oh[NX], g_Ol[NX];
__device__ bf16 g_Xh[NX], g_Xl[NX];
__device__ bf16 g_Wh[4 * NW], g_Wl[4 * NW];   // Wq, Wk, Wv, Wo

__device__ __forceinline__ float ex2f(float x) {
    float y;
    asm("ex2.approx.f32 %0, %1;" : "=f"(y) : "f"(x));
    return y;
}
// pack two floats -> bf16x2 {lo, hi}
__device__ __forceinline__ unsigned packbf2(float lo, float hi) {
    unsigned r;
    asm("cvt.rn.bf16x2.f32 %0, %1, %2;" : "=r"(r) : "f"(hi), "f"(lo));
    return r;
}
__device__ __forceinline__ float bfres(float v) {     // v - bf16(v)
    return v - __bfloat162float(__float2bfloat16(v));
}

// -------- warp-level bf16 MMA (validated in R13) --------
__device__ __forceinline__ void mma_bf16(float* d, const unsigned* a, const unsigned* b) {
    asm volatile(
        "mma.sync.aligned.m16n8k16.row.col.f32.bf16.bf16.f32 "
        "{%0,%1,%2,%3}, {%4,%5,%6,%7}, {%8,%9}, {%0,%1,%2,%3};"
        : "+f"(d[0]), "+f"(d[1]), "+f"(d[2]), "+f"(d[3])
        : "r"(a[0]), "r"(a[1]), "r"(a[2]), "r"(a[3]), "r"(b[0]), "r"(b[1]));
}

// =====================================================================
// Split fp32 -> (bf16 hi, bf16 lo): x and the four weight matrices.
// =====================================================================
__global__ __launch_bounds__(256) void split_in_kernel(const float* __restrict__ x,
                                                       const float* __restrict__ Wq,
                                                       const float* __restrict__ Wk,
                                                       const float* __restrict__ Wv,
                                                       const float* __restrict__ Wo)
{
    const int i = blockIdx.x * 256 + threadIdx.x;
    const int total = NX + 4 * NW;
    if (i >= total) return;
    float v;
    bf16 *hp, *lp;
    if (i < NX) {
        v = x[i];
        hp = g_Xh + i; lp = g_Xl + i;
    } else {
        int j = i - NX;
        int w = 0;
        while (j >= NW) { j -= NW; w++; }
        const float* src = (w == 0) ? Wq : (w == 1) ? Wk : (w == 2) ? Wv : Wo;
        v = src[j];
        hp = g_Wh + (i - NX); lp = g_Wl + (i - NX);
    }
    const bf16 h = __float2bfloat16(v);
    const bf16 l = __float2bfloat16(v - __bfloat162float(h));
    *hp = h; *lp = l;
}

// =====================================================================
// bf16-split GEMM on HMMA (validated R13): Y = A @ B^T (+bias).
// CTA 128x64, 8 warps, warp 64x16. Epilogue writes f32 and/or bf16 hi/lo.
// =====================================================================
#define MT 128
#define NT 64
#define KT 64
#define SPAD 72
#define SM_A (MT * SPAD)
#define SM_B (NT * SPAD)
#define MM_SMEM ((2 * SM_A + 2 * SM_B) * 2)

__device__ __forceinline__ void mm_core(const bf16* __restrict__ Ah,
                                        const bf16* __restrict__ Al,
                                        const bf16* __restrict__ Bh,
                                        const bf16* __restrict__ Bl,
                                        const float* __restrict__ bias,
                                        float* __restrict__ Yf,
                                        bf16* __restrict__ Yh,
                                        bf16* __restrict__ Yl)
{
    extern __shared__ __align__(16) unsigned char smraw[];
    bf16* sAh = (bf16*)smraw;
    bf16* sAl = sAh + SM_A;
    bf16* sBh = sAl + SM_A;
    bf16* sBl = sBh + SM_B;

    const int t    = threadIdx.x;
    const int wid  = t >> 5;
    const int lane = t & 31;
    const int gid  = lane >> 2;
    const int tig  = lane & 3;
    const int warp_m = (wid & 1) * 64;
    const int warp_n = (wid >> 1) * 16;
    const int row0 = blockIdx.x * MT;
    const int col0 = blockIdx.y * NT;

    float acc[4][2][4];
#pragma unroll
    for (int i = 0; i < 4; i++)
#pragma unroll
        for (int j = 0; j < 2; j++)
#pragma unroll
            for (int c = 0; c < 4; c++) acc[i][j][c] = 0.f;

    for (int kt = 0; kt < EDIM / KT; kt++) {
        const int kb = kt * KT;
        __syncthreads();
#pragma unroll
        for (int i = 0; i < 4; i++) {
            const int idx = t + i * 256;
            const int r = idx >> 3, c = (idx & 7) * 8;
            const size_t g = (size_t)(row0 + r) * EDIM + kb + c;
            *(uint4*)&sAh[r * SPAD + c] = *(const uint4*)&Ah[g];
            *(uint4*)&sAl[r * SPAD + c] = *(const uint4*)&Al[g];
        }
#pragma unroll
        for (int i = 0; i < 2; i++) {
            const int idx = t + i * 256;
            const int r = idx >> 3, c = (idx & 7) * 8;
            const size_t g = (size_t)(col0 + r) * EDIM + kb + c;
            *(uint4*)&sBh[r * SPAD + c] = *(const uint4*)&Bh[g];
            *(uint4*)&sBl[r * SPAD + c] = *(const uint4*)&Bl[g];
        }
        __syncthreads();

#pragma unroll
        for (int ks = 0; ks < KT / 16; ks++) {
            const int c0 = ks * 16 + tig * 2;
            const int c1 = c0 + 8;
            unsigned ah[4][4], al[4][4];
#pragma unroll
            for (int i = 0; i < 4; i++) {
                const int r0 = (warp_m + i * 16 + gid) * SPAD;
                const int r1 = r0 + 8 * SPAD;
                ah[i][0] = *(const unsigned*)&sAh[r0 + c0];
                ah[i][1] = *(const unsigned*)&sAh[r1 + c0];
                ah[i][2] = *(const unsigned*)&sAh[r0 + c1];
                ah[i][3] = *(const unsigned*)&sAh[r1 + c1];
                al[i][0] = *(const unsigned*)&sAl[r0 + c0];
                al[i][1] = *(const unsigned*)&sAl[r1 + c0];
                al[i][2] = *(const unsigned*)&sAl[r0 + c1];
                al[i][3] = *(const unsigned*)&sAl[r1 + c1];
            }
            unsigned bh[2][2], bl[2][2];
#pragma unroll
            for (int j = 0; j < 2; j++) {
                const int nr = (warp_n + j * 8 + gid) * SPAD;
                bh[j][0] = *(const unsigned*)&sBh[nr + c0];
                bh[j][1] = *(const unsigned*)&sBh[nr + c1];
                bl[j][0] = *(const unsigned*)&sBl[nr + c0];
                bl[j][1] = *(const unsigned*)&sBl[nr + c1];
            }
#pragma unroll
            for (int i = 0; i < 4; i++) {
#pragma unroll
                for (int j = 0; j < 2; j++) {
                    mma_bf16(acc[i][j], ah[i], bh[j]);
                    mma_bf16(acc[i][j], ah[i], bl[j]);
                    mma_bf16(acc[i][j], al[i], bh[j]);
                }
            }
        }
    }

#pragma unroll
    for (int i = 0; i < 4; i++) {
        const int row = row0 + warp_m + i * 16 + gid;
#pragma unroll
        for (int j = 0; j < 2; j++) {
            const int col = col0 + warp_n + j * 8 + tig * 2;
            float b0 = 0.f, b1 = 0.f;
            if (bias) { b0 = bias[col]; b1 = bias[col + 1]; }
            const float o0 = acc[i][j][0] + b0, o1 = acc[i][j][1] + b1;
            const float o2 = acc[i][j][2] + b0, o3 = acc[i][j][3] + b1;
            const size_t e0 = (size_t)row * EDIM + col;
            const size_t e1 = (size_t)(row + 8) * EDIM + col;
            if (Yf) {
                *(float2*)&Yf[e0] = make_float2(o0, o1);
                *(float2*)&Yf[e1] = make_float2(o2, o3);
            }
            if (Yh) {
                *(unsigned*)&Yh[e0] = packbf2(o0, o1);
                *(unsigned*)&Yh[e1] = packbf2(o2, o3);
                *(unsigned*)&Yl[e0] = packbf2(bfres(o0), bfres(o1));
                *(unsigned*)&Yl[e1] = packbf2(bfres(o2), bfres(o3));
            }
        }
    }
}

__global__ __launch_bounds__(256) void qkv_mm_kernel()
{
    const int z = blockIdx.z;
    bf16* Yh = (z == 0) ? g_Qh : (z == 1) ? g_Kh : g_Vh;
    bf16* Yl = (z == 0) ? g_Ql : (z == 1) ? g_Kl : g_Vl;
    float* Yf = (z == 2) ? g_V : nullptr;
    mm_core(g_Xh, g_Xl, g_Wh + (size_t)z * NW, g_Wl + (size_t)z * NW,
            nullptr, Yf, Yh, Yl);
}

__global__ __launch_bounds__(256) void out_mm_kernel(const float* __restrict__ bo,
                                                     float* __restrict__ Y)
{
    mm_core(g_Oh, g_Ol, g_Wh + 3 * (size_t)NW, g_Wl + 3 * (size_t)NW,
            bo, Y, nullptr, nullptr);
}

// =====================================================================
// Separable positional softmax (EXACT) — unchanged (reads g_V f32).
// =====================================================================
__global__ __launch_bounds__(256) void pos1_kernel(const float* __restrict__ Wpos)
{
    __shared__ float Vs[GRID_S][HDIM];
    __shared__ float fx[GRID_S][GRID_S];
    __shared__ float Zx[GRID_S];

    const int t  = threadIdx.x;
    const int my = blockIdx.x;
    const int h  = blockIdx.y;
    const int b  = blockIdx.z;
    const float LOG2E = 1.4426950408889634f;
    const float w0 = Wpos[h * 3 + 0];
    const float w2 = Wpos[h * 3 + 2];

    for (int i = t; i < GRID_S * HDIM; i += 256) {
        const int mx = i >> 5, d = i & 31;
        Vs[mx][d] = g_V[((size_t)(b * NPATCH + my * GRID_S + mx) * EDIM) + h * HDIM + d];
    }
    for (int i = t; i < GRID_S * GRID_S; i += 256) {
        const int qx = i / GRID_S, mx = i % GRID_S;
        const float dx = (float)(mx - qx);
        fx[qx][mx] = fmaf(w2, dx * dx, w0 * dx);
    }
    __syncthreads();
    if (t < GRID_S) {
        float mmax = -1e30f;
#pragma unroll
        for (int mx = 0; mx < GRID_S; mx++) mmax = fmaxf(mmax, fx[t][mx]);
        float z = 0.f;
#pragma unroll
        for (int mx = 0; mx < GRID_S; mx++) {
            const float f = ex2f((fx[t][mx] - mmax) * LOG2E);
            fx[t][mx] = f;
            z += f;
        }
        Zx[t] = z;
        g_Zx[h * GRID_S + t] = z;
    }
    __syncthreads();

    float* Tp = g_T + ((((size_t)(b * NHEAD + h) * GRID_S) * GRID_S) * HDIM);
    for (int i = t; i < GRID_S * HDIM; i += 256) {
        const int qx = i >> 5, d = i & 31;
        float s = 0.f;
#pragma unroll
        for (int mx = 0; mx < GRID_S; mx++) s = fmaf(fx[qx][mx], Vs[mx][d], s);
        Tp[((size_t)qx * GRID_S + my) * HDIM + d] = s;
    }
}

__global__ __launch_bounds__(256) void pos2_kernel(const float* __restrict__ Wpos,
                                                   const float* __restrict__ bpos)
{
    __shared__ float Ts[GRID_S][HDIM];
    __shared__ float fy[GRID_S][GRID_S];
    __shared__ float Zy[GRID_S];

    const int t  = threadIdx.x;
    const int qx = blockIdx.x;
    const int h  = blockIdx.y;
    const int b  = blockIdx.z;
    const float LOG2E = 1.4426950408889634f;
    const float w1 = Wpos[h * 3 + 1];
    const float w2 = Wpos[h * 3 + 2];
    const float bp = bpos[h];

    const float* Tp = g_T + ((((size_t)(b * NHEAD + h) * GRID_S + qx) * GRID_S) * HDIM);
    for (int i = t; i < GRID_S * HDIM; i += 256) {
        Ts[i >> 5][i & 31] = Tp[i];
    }
    for (int i = t; i < GRID_S * GRID_S; i += 256) {
        const int qy = i / GRID_S, my = i % GRID_S;
        const float dy = (float)(my - qy);
        fy[qy][my] = fmaf(w2, dy * dy, w1 * dy) + bp;
    }
    __syncthreads();
    if (t < GRID_S) {
        float mmax = -1e30f;
#pragma unroll
        for (int my = 0; my < GRID_S; my++) mmax = fmaxf(mmax, fy[t][my]);
        float z = 0.f;
#pragma unroll
        for (int my = 0; my < GRID_S; my++) {
            const float f = ex2f((fy[t][my] - mmax) * LOG2E);
            fy[t][my] = f;
            z += f;
        }
        Zy[t] = z;
    }
    __syncthreads();

    const float zx = g_Zx[h * GRID_S + qx];
    for (int i = t; i < GRID_S * HDIM; i += 256) {
        const int qy = i >> 5, d = i & 31;
        float s = 0.f;
#pragma unroll
        for (int my = 0; my < GRID_S; my++) s = fmaf(fy[qy][my], Ts[my][d], s);
        const int n = qy * GRID_S + qx;
        g_posO[(((size_t)(b * NHEAD + h) * NPATCH + n) * HDIM) + d] = s / (zx * Zy[qy]);
    }
}

// =====================================================================
// Flash attention on HMMA.
// Block = one (b,h) x 128 queries (8 warps x m16). Keys in 7 tiles of 112.
// QK: 3-term bf16 split, S in f32 frags. Softmax: no max-sub (bounded
// logits), row-sum by tig shfl. P reuses the S fragment layout as the
// A-operand (FA2 identity), split hi/lo. AV: 3-term with V transposed
// [dim][key] in smem. Epilogue blends posO + gating, writes Oh/Ol bf16.
// =====================================================================
#define AQ 128
#define AK 112
#define KPAD 40    // K tile row pitch (bf16)
#define VPAD 120   // V^T tile row pitch (bf16)

__global__ __launch_bounds__(256) void attn_kernel(const float* __restrict__ gating)
{
    __shared__ bf16 sKh[AK * KPAD];
    __shared__ bf16 sKl[AK * KPAD];
    __shared__ bf16 sVh[HDIM * VPAD];
    __shared__ bf16 sVl[HDIM * VPAD];

    const int t    = threadIdx.x;
    const int wid  = t >> 5;
    const int lane = t & 31;
    const int gid  = lane >> 2;
    const int tig  = lane & 3;
    const int h  = blockIdx.y;
    const int b  = blockIdx.z;
    const int n0 = blockIdx.x * AQ;

    const float C = 0.28867513459481287f * 1.4426950408889634f;  // scale*log2e

    // ---- Q fragments (2 k-steps of 16 dims), straight from gmem ----
    const int r0 = n0 + wid * 16 + gid;
    const int rq0 = (r0 < NPATCH) ? r0 : (NPATCH - 1);
    const int rq1 = (r0 + 8 < NPATCH) ? (r0 + 8) : (NPATCH - 1);
    const size_t qb0 = (size_t)(b * NPATCH + rq0) * EDIM + h * HDIM;
    const size_t qb1 = (size_t)(b * NPATCH + rq1) * EDIM + h * HDIM;
    unsigned qh[2][4], ql[2][4];
#pragma unroll
    for (int ks = 0; ks < 2; ks++) {
        const int c = tig * 2 + ks * 16;
        qh[ks][0] = *(const unsigned*)&g_Qh[qb0 + c];
        qh[ks][1] = *(const unsigned*)&g_Qh[qb1 + c];
        qh[ks][2] = *(const unsigned*)&g_Qh[qb0 + c + 8];
        qh[ks][3] = *(const unsigned*)&g_Qh[qb1 + c + 8];
        ql[ks][0] = *(const unsigned*)&g_Ql[qb0 + c];
        ql[ks][1] = *(const unsigned*)&g_Ql[qb1 + c];
        ql[ks][2] = *(const unsigned*)&g_Ql[qb0 + c + 8];
        ql[ks][3] = *(const unsigned*)&g_Ql[qb1 + c + 8];
    }

    float O[4][4];
#pragma unroll
    for (int j = 0; j < 4; j++)
#pragma unroll
        for (int c = 0; c < 4; c++) O[j][c] = 0.f;
    float zp0 = 0.f, zp1 = 0.f;

    for (int m0 = 0; m0 < NPATCH; m0 += AK) {
        __syncthreads();
        // K tile: [key][dim], 112x32, uint4 loads
        for (int i = t; i < AK * 4; i += 256) {
            const int r = i >> 2, c = (i & 3) * 8;
            const size_t g = (size_t)(b * NPATCH + m0 + r) * EDIM + h * HDIM + c;
            *(uint4*)&sKh[r * KPAD + c] = *(const uint4*)&g_Kh[g];
            *(uint4*)&sKl[r * KPAD + c] = *(const uint4*)&g_Kl[g];
        }
        // V tile transposed: [dim][key], element scatter from uint reads
        for (int i = t; i < AK * 16; i += 256) {
            const int k = i >> 4, d2 = (i & 15);
            const size_t g = (size_t)(b * NPATCH + m0 + k) * EDIM + h * HDIM + d2 * 2;
            const unsigned uh = *(const unsigned*)&g_Vh[g];
            const unsigned ul = *(const unsigned*)&g_Vl[g];
            ((unsigned short*)sVh)[(d2 * 2) * VPAD + k]     = (unsigned short)(uh & 0xffff);
            ((unsigned short*)sVh)[(d2 * 2 + 1) * VPAD + k] = (unsigned short)(uh >> 16);
            ((unsigned short*)sVl)[(d2 * 2) * VPAD + k]     = (unsigned short)(ul & 0xffff);
            ((unsigned short*)sVl)[(d2 * 2 + 1) * VPAD + k] = (unsigned short)(ul >> 16);
        }
        __syncthreads();

        // ---- S = Q K^T (f32 frags, 14 n-frags of 8 keys) ----
        float S[14][4];
#pragma unroll
        for (int j = 0; j < 14; j++)
#pragma unroll
            for (int c = 0; c < 4; c++) S[j][c] = 0.f;
#pragma unroll
        for (int ks = 0; ks < 2; ks++) {
#pragma unroll
            for (int j = 0; j < 14; j++) {
                const int off = (j * 8 + gid) * KPAD + tig * 2 + ks * 16;
                unsigned kb[2], kl2[2];
                kb[0]  = *(const unsigned*)&sKh[off];
                kb[1]  = *(const unsigned*)&sKh[off + 8];
                kl2[0] = *(const unsigned*)&sKl[off];
                kl2[1] = *(const unsigned*)&sKl[off + 8];
                mma_bf16(S[j], qh[ks], kb);
                mma_bf16(S[j], ql[ks], kb);
                mma_bf16(S[j], qh[ks], kl2);
            }
        }

        // ---- softmax weights + AV, per 16-key group ----
#pragma unroll
        for (int ks2 = 0; ks2 < 7; ks2++) {
            const int j0 = 2 * ks2, j1 = j0 + 1;
            float w00 = ex2f(S[j0][0] * C), w01 = ex2f(S[j0][1] * C);
            float w02 = ex2f(S[j0][2] * C), w03 = ex2f(S[j0][3] * C);
            float w10 = ex2f(S[j1][0] * C), w11 = ex2f(S[j1][1] * C);
            float w12 = ex2f(S[j1][2] * C), w13 = ex2f(S[j1][3] * C);
            zp0 += (w00 + w01) + (w10 + w11);
            zp1 += (w02 + w03) + (w12 + w13);
            unsigned aPh[4], aPl[4];
            aPh[0] = packbf2(w00, w01);
            aPh[1] = packbf2(w02, w03);
            aPh[2] = packbf2(w10, w11);
            aPh[3] = packbf2(w12, w13);
            aPl[0] = packbf2(bfres(w00), bfres(w01));
            aPl[1] = packbf2(bfres(w02), bfres(w03));
            aPl[2] = packbf2(bfres(w10), bfres(w11));
            aPl[3] = packbf2(bfres(w12), bfres(w13));
#pragma unroll
            for (int jd = 0; jd < 4; jd++) {
                const int off = (jd * 8 + gid) * VPAD + tig * 2 + ks2 * 16;
                unsigned vbh[2], vbl[2];
                vbh[0] = *(const unsigned*)&sVh[off];
                vbh[1] = *(const unsigned*)&sVh[off + 8];
                vbl[0] = *(const unsigned*)&sVl[off];
                vbl[1] = *(const unsigned*)&sVl[off + 8];
                mma_bf16(O[jd], aPh, vbh);
                mma_bf16(O[jd], aPl, vbh);
                mma_bf16(O[jd], aPh, vbl);
            }
        }
    }

    // full row sums across the tig group
    zp0 += __shfl_xor_sync(0xffffffffu, zp0, 1);
    zp0 += __shfl_xor_sync(0xffffffffu, zp0, 2);
    zp1 += __shfl_xor_sync(0xffffffffu, zp1, 1);
    zp1 += __shfl_xor_sync(0xffffffffu, zp1, 2);

    const float g  = gating[h];
    const float sg = 1.f / (1.f + ex2f(-g * 1.4426950408889634f));
    const float cP0 = (1.f - sg) / zp0;
    const float cP1 = (1.f - sg) / zp1;

    const int rw0 = n0 + wid * 16 + gid;
    const int rw1 = rw0 + 8;
#pragma unroll
    for (int jd = 0; jd < 4; jd++) {
        const int d = jd * 8 + tig * 2;
        if (rw0 < NPATCH) {
            const float2 ps = *(const float2*)&g_posO[(((size_t)(b * NHEAD + h) * NPATCH + rw0) * HDIM) + d];
            const float o0 = fmaf(cP0, O[jd][0], sg * ps.x);
            const float o1 = fmaf(cP0, O[jd][1], sg * ps.y);
            const size_t e = (size_t)(b * NPATCH + rw0) * EDIM + h * HDIM + d;
            *(unsigned*)&g_Oh[e] = packbf2(o0, o1);
            *(unsigned*)&g_Ol[e] = packbf2(bfres(o0), bfres(o1));
        }
        if (rw1 < NPATCH) {
            const float2 ps = *(const float2*)&g_posO[(((size_t)(b * NHEAD + h) * NPATCH + rw1) * HDIM) + d];
            const float o2 = fmaf(cP1, O[jd][2], sg * ps.x);
            const float o3 = fmaf(cP1, O[jd][3], sg * ps.y);
            const size_t e = (size_t)(b * NPATCH + rw1) * EDIM + h * HDIM + d;
            *(unsigned*)&g_Oh[e] = packbf2(o2, o3);
            *(unsigned*)&g_Ol[e] = packbf2(bfres(o2), bfres(o3));
        }
    }
}

// =====================================================================
extern "C" void kernel_launch(void* const* d_in, const int* in_sizes, int n_in,
                              void* d_out, int out_size)
{
    const float* x   = (const float*)d_in[0];
    const float* Wq  = (const float*)d_in[1];
    const float* Wk  = (const float*)d_in[2];
    const float* Wv  = (const float*)d_in[3];
    const float* Wp  = (const float*)d_in[4];
    const float* bp  = (const float*)d_in[5];
    const float* Wo  = (const float*)d_in[6];
    const float* bo  = (const float*)d_in[7];
    const float* gt  = (const float*)d_in[8];
    float* out = (float*)d_out;

    cudaFuncSetAttribute(qkv_mm_kernel, cudaFuncAttributeMaxDynamicSharedMemorySize, MM_SMEM);
    cudaFuncSetAttribute(out_mm_kernel, cudaFuncAttributeMaxDynamicSharedMemorySize, MM_SMEM);

    // 1. split x + weights
    split_in_kernel<<<(NX + 4 * NW + 255) / 256, 256>>>(x, Wq, Wk, Wv, Wo);

    // 2. Q,K,V projections (HMMA) -> bf16 hi/lo (+ f32 V for pos)
    dim3 gq(49, 6, 3);
    qkv_mm_kernel<<<gq, 256, MM_SMEM>>>();

    // 3. positional softmax (separable, exact)
    dim3 gp1(GRID_S, NHEAD, BATCH);
    pos1_kernel<<<gp1, 256>>>(Wp);
    pos2_kernel<<<gp1, 256>>>(Wp, bp);

    // 4. flash attention (HMMA) + blend -> Oh/Ol
    dim3 ga((NPATCH + AQ - 1) / AQ, NHEAD, BATCH);   // (7, 12, 8)
    attn_kernel<<<ga, 256>>>(gt);

    // 5. output projection (HMMA)
    dim3 go(49, 6, 1);
    out_mm_kernel<<<go, 256, MM_SMEM>>>(bo, out);
}

// round 15
// speedup vs baseline: 3.1374x; 1.1706x over previous
#include <cuda_runtime.h>
#include <cuda_bf16.h>

#define BATCH   8
#define NPATCH  784
#define EDIM    384
#define NHEAD   12
#define HDIM    32
#define GRID_S  28

#define NX (BATCH * NPATCH * EDIM)   // 2408448
#define NW (EDIM * EDIM)             // 147456

typedef unsigned long long ull;
typedef __nv_bfloat16 bf16;

// -------- scratch (no allocations allowed) --------
__device__ float g_V[NX];                              // f32 V (pos kernels)
__device__ float g_posO[BATCH * NHEAD * NPATCH * HDIM];
__device__ float g_T[BATCH * NHEAD * GRID_S * GRID_S * HDIM];
__device__ float g_Zx[NHEAD * GRID_S];
__device__ bf16 g_Qh[NX], g_Ql[NX];    // pre-scaled by scale*log2e
__device__ bf16 g_Kh[NX], g_Kl[NX];
__device__ bf16 g_Vh[NX], g_Vl[NX];
__device__ bf16 g_Oh[NX], g_Ol[NX];
__device__ bf16 g_Xh[NX], g_Xl[NX];
__device__ bf16 g_Wh[4 * NW], g_Wl[4 * NW];   // Wq, Wk, Wv, Wo

__device__ __forceinline__ float ex2f(float x) {
    float y;
    asm("ex2.approx.f32 %0, %1;" : "=f"(y) : "f"(x));
    return y;
}
__device__ __forceinline__ unsigned packbf2(float lo, float hi) {
    unsigned r;
    asm("cvt.rn.bf16x2.f32 %0, %1, %2;" : "=r"(r) : "f"(hi), "f"(lo));
    return r;
}
__device__ __forceinline__ float bfres(float v) {
    return v - __bfloat162float(__float2bfloat16(v));
}
__device__ __forceinline__ unsigned s2u(const void* p) {
    unsigned a;
    asm("{ .reg .u64 t; cvta.to.shared.u64 t, %1; cvt.u32.u64 %0, t; }" : "=r"(a) : "l"(p));
    return a;
}
__device__ __forceinline__ void cpasync16(unsigned saddr, const void* g) {
    asm volatile("cp.async.cg.shared.global [%0], [%1], 16;" :: "r"(saddr), "l"(g));
}
__device__ __forceinline__ void cp_commit() {
    asm volatile("cp.async.commit_group;" ::: "memory");
}
__device__ __forceinline__ void cp_wait1() {
    asm volatile("cp.async.wait_group 1;" ::: "memory");
}
__device__ __forceinline__ void cp_wait0() {
    asm volatile("cp.async.wait_group 0;" ::: "memory");
}
__device__ __forceinline__ void ldmx2t(unsigned& r0, unsigned& r1, unsigned saddr) {
    asm volatile("ldmatrix.sync.aligned.m8n8.x2.trans.shared.b16 {%0,%1}, [%2];"
                 : "=r"(r0), "=r"(r1) : "r"(saddr));
}

// -------- warp-level bf16 MMA (validated R13/R14) --------
__device__ __forceinline__ void mma_bf16(float* d, const unsigned* a, const unsigned* b) {
    asm volatile(
        "mma.sync.aligned.m16n8k16.row.col.f32.bf16.bf16.f32 "
        "{%0,%1,%2,%3}, {%4,%5,%6,%7}, {%8,%9}, {%0,%1,%2,%3};"
        : "+f"(d[0]), "+f"(d[1]), "+f"(d[2]), "+f"(d[3])
        : "r"(a[0]), "r"(a[1]), "r"(a[2]), "r"(a[3]), "r"(b[0]), "r"(b[1]));
}

// =====================================================================
// Split fp32 -> (bf16 hi, bf16 lo): x and the four weight matrices.
// =====================================================================
__global__ __launch_bounds__(256) void split_in_kernel(const float* __restrict__ x,
                                                       const float* __restrict__ Wq,
                                                       const float* __restrict__ Wk,
                                                       const float* __restrict__ Wv,
                                                       const float* __restrict__ Wo)
{
    const int i = blockIdx.x * 256 + threadIdx.x;
    const int total = NX + 4 * NW;
    if (i >= total) return;
    float v;
    bf16 *hp, *lp;
    if (i < NX) {
        v = x[i];
        hp = g_Xh + i; lp = g_Xl + i;
    } else {
        int j = i - NX;
        int w = 0;
        while (j >= NW) { j -= NW; w++; }
        const float* src = (w == 0) ? Wq : (w == 1) ? Wk : (w == 2) ? Wv : Wo;
        v = src[j];
        hp = g_Wh + (i - NX); lp = g_Wl + (i - NX);
    }
    const bf16 h = __float2bfloat16(v);
    const bf16 l = __float2bfloat16(v - __bfloat162float(h));
    *hp = h; *lp = l;
}

// =====================================================================
// bf16-split GEMM on HMMA with cp.async double-buffered K-slabs.
// CTA 128x64, 8 warps, warp 64x16; fragment math identical to R14.
// =====================================================================
#define MT 128
#define NT 64
#define KT 64
#define SPAD 72
#define SM_A (MT * SPAD)
#define SM_B (NT * SPAD)
#define MM_STAGE (2 * SM_A + 2 * SM_B)      // bf16 elements per stage
#define MM_SMEM (2 * MM_STAGE * 2)          // bytes = 110592

__device__ __forceinline__ void mm_core(const bf16* __restrict__ Ah,
                                        const bf16* __restrict__ Al,
                                        const bf16* __restrict__ Bh,
                                        const bf16* __restrict__ Bl,
                                        const float* __restrict__ bias,
                                        float oscale,
                                        float* __restrict__ Yf,
                                        bf16* __restrict__ Yh,
                                        bf16* __restrict__ Yl)
{
    extern __shared__ __align__(16) unsigned char smraw[];
    const unsigned sbase = s2u(smraw);

    const int t    = threadIdx.x;
    const int wid  = t >> 5;
    const int lane = t & 31;
    const int gid  = lane >> 2;
    const int tig  = lane & 3;
    const int warp_m = (wid & 1) * 64;
    const int warp_n = (wid >> 1) * 16;
    const int row0 = blockIdx.x * MT;
    const int col0 = blockIdx.y * NT;

    float acc[4][2][4];
#pragma unroll
    for (int i = 0; i < 4; i++)
#pragma unroll
        for (int j = 0; j < 2; j++)
#pragma unroll
            for (int c = 0; c < 4; c++) acc[i][j][c] = 0.f;

    // async issue of one 64-wide K-slab into stage `buf`
    auto issue = [&](int kt, int buf) {
        const int kb = kt * KT;
        const unsigned s0 = sbase + (unsigned)buf * (MM_STAGE * 2);
#pragma unroll
        for (int i = 0; i < 4; i++) {
            const int idx = t + i * 256;
            const int r = idx >> 3, c = (idx & 7) * 8;
            const size_t g = (size_t)(row0 + r) * EDIM + kb + c;
            const unsigned off = (unsigned)(r * SPAD + c) * 2;
            cpasync16(s0 + off, &Ah[g]);
            cpasync16(s0 + SM_A * 2 + off, &Al[g]);
        }
#pragma unroll
        for (int i = 0; i < 2; i++) {
            const int idx = t + i * 256;
            const int r = idx >> 3, c = (idx & 7) * 8;
            const size_t g = (size_t)(col0 + r) * EDIM + kb + c;
            const unsigned off = (unsigned)(r * SPAD + c) * 2;
            cpasync16(s0 + (2 * SM_A) * 2 + off, &Bh[g]);
            cpasync16(s0 + (2 * SM_A + SM_B) * 2 + off, &Bl[g]);
        }
        cp_commit();
    };

    issue(0, 0);
    for (int kt = 0; kt < EDIM / KT; kt++) {
        const bool more = (kt + 1 < EDIM / KT);
        if (more) issue(kt + 1, (kt + 1) & 1);
        if (more) cp_wait1(); else cp_wait0();
        __syncthreads();

        const bf16* sAh = (const bf16*)smraw + (kt & 1) * MM_STAGE;
        const bf16* sAl = sAh + SM_A;
        const bf16* sBh = sAl + SM_A;
        const bf16* sBl = sBh + SM_B;

#pragma unroll
        for (int ks = 0; ks < KT / 16; ks++) {
            const int c0 = ks * 16 + tig * 2;
            const int c1 = c0 + 8;
            unsigned ah[4][4], al[4][4];
#pragma unroll
            for (int i = 0; i < 4; i++) {
                const int r0 = (warp_m + i * 16 + gid) * SPAD;
                const int r1 = r0 + 8 * SPAD;
                ah[i][0] = *(const unsigned*)&sAh[r0 + c0];
                ah[i][1] = *(const unsigned*)&sAh[r1 + c0];
                ah[i][2] = *(const unsigned*)&sAh[r0 + c1];
                ah[i][3] = *(const unsigned*)&sAh[r1 + c1];
                al[i][0] = *(const unsigned*)&sAl[r0 + c0];
                al[i][1] = *(const unsigned*)&sAl[r1 + c0];
                al[i][2] = *(const unsigned*)&sAl[r0 + c1];
                al[i][3] = *(const unsigned*)&sAl[r1 + c1];
            }
            unsigned bh[2][2], bl[2][2];
#pragma unroll
            for (int j = 0; j < 2; j++) {
                const int nr = (warp_n + j * 8 + gid) * SPAD;
                bh[j][0] = *(const unsigned*)&sBh[nr + c0];
                bh[j][1] = *(const unsigned*)&sBh[nr + c1];
                bl[j][0] = *(const unsigned*)&sBl[nr + c0];
                bl[j][1] = *(const unsigned*)&sBl[nr + c1];
            }
#pragma unroll
            for (int i = 0; i < 4; i++) {
#pragma unroll
                for (int j = 0; j < 2; j++) {
                    mma_bf16(acc[i][j], ah[i], bh[j]);
                    mma_bf16(acc[i][j], ah[i], bl[j]);
                    mma_bf16(acc[i][j], al[i], bh[j]);
                }
            }
        }
        __syncthreads();
    }

#pragma unroll
    for (int i = 0; i < 4; i++) {
        const int row = row0 + warp_m + i * 16 + gid;
#pragma unroll
        for (int j = 0; j < 2; j++) {
            const int col = col0 + warp_n + j * 8 + tig * 2;
            float b0 = 0.f, b1 = 0.f;
            if (bias) { b0 = bias[col]; b1 = bias[col + 1]; }
            const float o0 = fmaf(acc[i][j][0], oscale, b0);
            const float o1 = fmaf(acc[i][j][1], oscale, b1);
            const float o2 = fmaf(acc[i][j][2], oscale, b0);
            const float o3 = fmaf(acc[i][j][3], oscale, b1);
            const size_t e0 = (size_t)row * EDIM + col;
            const size_t e1 = (size_t)(row + 8) * EDIM + col;
            if (Yf) {
                *(float2*)&Yf[e0] = make_float2(o0, o1);
                *(float2*)&Yf[e1] = make_float2(o2, o3);
            }
            if (Yh) {
                *(unsigned*)&Yh[e0] = packbf2(o0, o1);
                *(unsigned*)&Yh[e1] = packbf2(o2, o3);
                *(unsigned*)&Yl[e0] = packbf2(bfres(o0), bfres(o1));
                *(unsigned*)&Yl[e1] = packbf2(bfres(o2), bfres(o3));
            }
        }
    }
}

#define QSCALE 0.41647617814089046f   // 12^-0.5 * log2(e)

__global__ __launch_bounds__(256) void qkv_mm_kernel()
{
    const int z = blockIdx.z;
    bf16* Yh = (z == 0) ? g_Qh : (z == 1) ? g_Kh : g_Vh;
    bf16* Yl = (z == 0) ? g_Ql : (z == 1) ? g_Kl : g_Vl;
    float* Yf = (z == 2) ? g_V : nullptr;
    const float sc = (z == 0) ? QSCALE : 1.0f;
    mm_core(g_Xh, g_Xl, g_Wh + (size_t)z * NW, g_Wl + (size_t)z * NW,
            nullptr, sc, Yf, Yh, Yl);
}

__global__ __launch_bounds__(256) void out_mm_kernel(const float* __restrict__ bo,
                                                     float* __restrict__ Y)
{
    mm_core(g_Oh, g_Ol, g_Wh + 3 * (size_t)NW, g_Wl + 3 * (size_t)NW,
            bo, 1.0f, Y, nullptr, nullptr);
}

// =====================================================================
// Separable positional softmax (EXACT) — unchanged.
// =====================================================================
__global__ __launch_bounds__(256) void pos1_kernel(const float* __restrict__ Wpos)
{
    __shared__ float Vs[GRID_S][HDIM];
    __shared__ float fx[GRID_S][GRID_S];
    __shared__ float Zx[GRID_S];

    const int t  = threadIdx.x;
    const int my = blockIdx.x;
    const int h  = blockIdx.y;
    const int b  = blockIdx.z;
    const float LOG2E = 1.4426950408889634f;
    const float w0 = Wpos[h * 3 + 0];
    const float w2 = Wpos[h * 3 + 2];

    for (int i = t; i < GRID_S * HDIM; i += 256) {
        const int mx = i >> 5, d = i & 31;
        Vs[mx][d] = g_V[((size_t)(b * NPATCH + my * GRID_S + mx) * EDIM) + h * HDIM + d];
    }
    for (int i = t; i < GRID_S * GRID_S; i += 256) {
        const int qx = i / GRID_S, mx = i % GRID_S;
        const float dx = (float)(mx - qx);
        fx[qx][mx] = fmaf(w2, dx * dx, w0 * dx);
    }
    __syncthreads();
    if (t < GRID_S) {
        float mmax = -1e30f;
#pragma unroll
        for (int mx = 0; mx < GRID_S; mx++) mmax = fmaxf(mmax, fx[t][mx]);
        float z = 0.f;
#pragma unroll
        for (int mx = 0; mx < GRID_S; mx++) {
            const float f = ex2f((fx[t][mx] - mmax) * LOG2E);
            fx[t][mx] = f;
            z += f;
        }
        Zx[t] = z;
        g_Zx[h * GRID_S + t] = z;
    }
    __syncthreads();

    float* Tp = g_T + ((((size_t)(b * NHEAD + h) * GRID_S) * GRID_S) * HDIM);
    for (int i = t; i < GRID_S * HDIM; i += 256) {
        const int qx = i >> 5, d = i & 31;
        float s = 0.f;
#pragma unroll
        for (int mx = 0; mx < GRID_S; mx++) s = fmaf(fx[qx][mx], Vs[mx][d], s);
        Tp[((size_t)qx * GRID_S + my) * HDIM + d] = s;
    }
}

__global__ __launch_bounds__(256) void pos2_kernel(const float* __restrict__ Wpos,
                                                   const float* __restrict__ bpos)
{
    __shared__ float Ts[GRID_S][HDIM];
    __shared__ float fy[GRID_S][GRID_S];
    __shared__ float Zy[GRID_S];

    const int t  = threadIdx.x;
    const int qx = blockIdx.x;
    const int h  = blockIdx.y;
    const int b  = blockIdx.z;
    const float LOG2E = 1.4426950408889634f;
    const float w1 = Wpos[h * 3 + 1];
    const float w2 = Wpos[h * 3 + 2];
    const float bp = bpos[h];

    const float* Tp = g_T + ((((size_t)(b * NHEAD + h) * GRID_S + qx) * GRID_S) * HDIM);
    for (int i = t; i < GRID_S * HDIM; i += 256) {
        Ts[i >> 5][i & 31] = Tp[i];
    }
    for (int i = t; i < GRID_S * GRID_S; i += 256) {
        const int qy = i / GRID_S, my = i % GRID_S;
        const float dy = (float)(my - qy);
        fy[qy][my] = fmaf(w2, dy * dy, w1 * dy) + bp;
    }
    __syncthreads();
    if (t < GRID_S) {
        float mmax = -1e30f;
#pragma unroll
        for (int my = 0; my < GRID_S; my++) mmax = fmaxf(mmax, fy[t][my]);
        float z = 0.f;
#pragma unroll
        for (int my = 0; my < GRID_S; my++) {
            const float f = ex2f((fy[t][my] - mmax) * LOG2E);
            fy[t][my] = f;
            z += f;
        }
        Zy[t] = z;
    }
    __syncthreads();

    const float zx = g_Zx[h * GRID_S + qx];
    for (int i = t; i < GRID_S * HDIM; i += 256) {
        const int qy = i >> 5, d = i & 31;
        float s = 0.f;
#pragma unroll
        for (int my = 0; my < GRID_S; my++) s = fmaf(fy[qy][my], Ts[my][d], s);
        const int n = qy * GRID_S + qx;
        g_posO[(((size_t)(b * NHEAD + h) * NPATCH + n) * HDIM) + d] = s / (zx * Zy[qy]);
    }
}

// =====================================================================
// Flash attention on HMMA, cp.async double-buffered K/V tiles.
// V stored [key][dim] (same as K); B-fragments for AV via ldmatrix.trans.
// Q pre-scaled by scale*log2e at projection time.
// =====================================================================
#define AQ 128
#define AK 112
#define KPAD 40
#define A_ONE (AK * KPAD)               // bf16 elems per array (4480)
#define A_STAGE (4 * A_ONE)             // Kh,Kl,Vh,Vl
#define ATTN_SMEM (2 * A_STAGE * 2)     // bytes = 71680

__global__ __launch_bounds__(256) void attn_kernel(const float* __restrict__ gating)
{
    extern __shared__ __align__(16) unsigned char smraw[];
    const unsigned sbase = s2u(smraw);

    const int t    = threadIdx.x;
    const int wid  = t >> 5;
    const int lane = t & 31;
    const int gid  = lane >> 2;
    const int tig  = lane & 3;
    const int h  = blockIdx.y;
    const int b  = blockIdx.z;
    const int n0 = blockIdx.x * AQ;

    // ---- Q fragments (pre-scaled) ----
    const int r0 = n0 + wid * 16 + gid;
    const int rq0 = (r0 < NPATCH) ? r0 : (NPATCH - 1);
    const int rq1 = (r0 + 8 < NPATCH) ? (r0 + 8) : (NPATCH - 1);
    const size_t qb0 = (size_t)(b * NPATCH + rq0) * EDIM + h * HDIM;
    const size_t qb1 = (size_t)(b * NPATCH + rq1) * EDIM + h * HDIM;
    unsigned qh[2][4], ql[2][4];
#pragma unroll
    for (int ks = 0; ks < 2; ks++) {
        const int c = tig * 2 + ks * 16;
        qh[ks][0] = *(const unsigned*)&g_Qh[qb0 + c];
        qh[ks][1] = *(const unsigned*)&g_Qh[qb1 + c];
        qh[ks][2] = *(const unsigned*)&g_Qh[qb0 + c + 8];
        qh[ks][3] = *(const unsigned*)&g_Qh[qb1 + c + 8];
        ql[ks][0] = *(const unsigned*)&g_Ql[qb0 + c];
        ql[ks][1] = *(const unsigned*)&g_Ql[qb1 + c];
        ql[ks][2] = *(const unsigned*)&g_Ql[qb0 + c + 8];
        ql[ks][3] = *(const unsigned*)&g_Ql[qb1 + c + 8];
    }

    float O[4][4];
#pragma unroll
    for (int j = 0; j < 4; j++)
#pragma unroll
        for (int c = 0; c < 4; c++) O[j][c] = 0.f;
    float zp0 = 0.f, zp1 = 0.f;

    // async issue of one K/V tile into stage `buf`
    auto issue = [&](int m0, int buf) {
        const unsigned s0 = sbase + (unsigned)buf * (A_STAGE * 2);
#pragma unroll
        for (int i = 0; i < 7; i++) {
            const int idx = t + i * 256;           // 0..1791
            const int arr = idx / 448;             // 0 Kh, 1 Kl, 2 Vh, 3 Vl
            const int rem = idx - arr * 448;
            const int r = rem >> 2, c = (rem & 3) * 8;
            const size_t g = (size_t)(b * NPATCH + m0 + r) * EDIM + h * HDIM + c;
            const bf16* src = (arr == 0) ? g_Kh : (arr == 1) ? g_Kl
                            : (arr == 2) ? g_Vh : g_Vl;
            cpasync16(s0 + (unsigned)(arr * A_ONE + r * KPAD + c) * 2, &src[g]);
        }
        cp_commit();
    };

    issue(0, 0);
    for (int mt = 0; mt < 7; mt++) {
        const bool more = (mt + 1 < 7);
        if (more) issue((mt + 1) * AK, (mt + 1) & 1);
        if (more) cp_wait1(); else cp_wait0();
        __syncthreads();

        const bf16* sKh = (const bf16*)smraw + (mt & 1) * A_STAGE;
        const bf16* sKl = sKh + A_ONE;
        const unsigned vhb = sbase + (unsigned)((mt & 1) * A_STAGE + 2 * A_ONE) * 2;
        const unsigned vlb = vhb + (unsigned)A_ONE * 2;

        // ---- S = Q K^T ----
        float S[14][4];
#pragma unroll
        for (int j = 0; j < 14; j++)
#pragma unroll
            for (int c = 0; c < 4; c++) S[j][c] = 0.f;
#pragma unroll
        for (int ks = 0; ks < 2; ks++) {
#pragma unroll
            for (int j = 0; j < 14; j++) {
                const int off = (j * 8 + gid) * KPAD + tig * 2 + ks * 16;
                unsigned kb[2], kl2[2];
                kb[0]  = *(const unsigned*)&sKh[off];
                kb[1]  = *(const unsigned*)&sKh[off + 8];
                kl2[0] = *(const unsigned*)&sKl[off];
                kl2[1] = *(const unsigned*)&sKl[off + 8];
                mma_bf16(S[j], qh[ks], kb);
                mma_bf16(S[j], ql[ks], kb);
                mma_bf16(S[j], qh[ks], kl2);
            }
        }

        // ---- softmax weights + AV ----
#pragma unroll
        for (int ks2 = 0; ks2 < 7; ks2++) {
            const int j0 = 2 * ks2, j1 = j0 + 1;
            float w00 = ex2f(S[j0][0]), w01 = ex2f(S[j0][1]);
            float w02 = ex2f(S[j0][2]), w03 = ex2f(S[j0][3]);
            float w10 = ex2f(S[j1][0]), w11 = ex2f(S[j1][1]);
            float w12 = ex2f(S[j1][2]), w13 = ex2f(S[j1][3]);
            zp0 += (w00 + w01) + (w10 + w11);
            zp1 += (w02 + w03) + (w12 + w13);
            unsigned aPh[4], aPl[4];
            aPh[0] = packbf2(w00, w01);
            aPh[1] = packbf2(w02, w03);
            aPh[2] = packbf2(w10, w11);
            aPh[3] = packbf2(w12, w13);
            aPl[0] = packbf2(bfres(w00), bfres(w01));
            aPl[1] = packbf2(bfres(w02), bfres(w03));
            aPl[2] = packbf2(bfres(w10), bfres(w11));
            aPl[3] = packbf2(bfres(w12), bfres(w13));
            const unsigned krow = (unsigned)((ks2 * 16 + (lane & 15)) * KPAD) * 2;
#pragma unroll
            for (int jd = 0; jd < 4; jd++) {
                unsigned vbh[2], vbl[2];
                ldmx2t(vbh[0], vbh[1], vhb + krow + (unsigned)(jd * 8) * 2);
                ldmx2t(vbl[0], vbl[1], vlb + krow + (unsigned)(jd * 8) * 2);
                mma_bf16(O[jd], aPh, vbh);
                mma_bf16(O[jd], aPl, vbh);
                mma_bf16(O[jd], aPh, vbl);
            }
        }
        __syncthreads();
    }

    zp0 += __shfl_xor_sync(0xffffffffu, zp0, 1);
    zp0 += __shfl_xor_sync(0xffffffffu, zp0, 2);
    zp1 += __shfl_xor_sync(0xffffffffu, zp1, 1);
    zp1 += __shfl_xor_sync(0xffffffffu, zp1, 2);

    const float g  = gating[h];
    const float sg = 1.f / (1.f + ex2f(-g * 1.4426950408889634f));
    const float cP0 = (1.f - sg) / zp0;
    const float cP1 = (1.f - sg) / zp1;

    const int rw0 = n0 + wid * 16 + gid;
    const int rw1 = rw0 + 8;
#pragma unroll
    for (int jd = 0; jd < 4; jd++) {
        const int d = jd * 8 + tig * 2;
        if (rw0 < NPATCH) {
            const float2 ps = *(const float2*)&g_posO[(((size_t)(b * NHEAD + h) * NPATCH + rw0) * HDIM) + d];
            const float o0 = fmaf(cP0, O[jd][0], sg * ps.x);
            const float o1 = fmaf(cP0, O[jd][1], sg * ps.y);
            const size_t e = (size_t)(b * NPATCH + rw0) * EDIM + h * HDIM + d;
            *(unsigned*)&g_Oh[e] = packbf2(o0, o1);
            *(unsigned*)&g_Ol[e] = packbf2(bfres(o0), bfres(o1));
        }
        if (rw1 < NPATCH) {
            const float2 ps = *(const float2*)&g_posO[(((size_t)(b * NHEAD + h) * NPATCH + rw1) * HDIM) + d];
            const float o2 = fmaf(cP1, O[jd][2], sg * ps.x);
            const float o3 = fmaf(cP1, O[jd][3], sg * ps.y);
            const size_t e = (size_t)(b * NPATCH + rw1) * EDIM + h * HDIM + d;
            *(unsigned*)&g_Oh[e] = packbf2(o2, o3);
            *(unsigned*)&g_Ol[e] = packbf2(bfres(o2), bfres(o3));
        }
    }
}

// =====================================================================
extern "C" void kernel_launch(void* const* d_in, const int* in_sizes, int n_in,
                              void* d_out, int out_size)
{
    const float* x   = (const float*)d_in[0];
    const float* Wq  = (const float*)d_in[1];
    const float* Wk  = (const float*)d_in[2];
    const float* Wv  = (const float*)d_in[3];
    const float* Wp  = (const float*)d_in[4];
    const float* bp  = (const float*)d_in[5];
    const float* Wo  = (const float*)d_in[6];
    const float* bo  = (const float*)d_in[7];
    const float* gt  = (const float*)d_in[8];
    float* out = (float*)d_out;

    cudaFuncSetAttribute(qkv_mm_kernel, cudaFuncAttributeMaxDynamicSharedMemorySize, MM_SMEM);
    cudaFuncSetAttribute(out_mm_kernel, cudaFuncAttributeMaxDynamicSharedMemorySize, MM_SMEM);
    cudaFuncSetAttribute(attn_kernel, cudaFuncAttributeMaxDynamicSharedMemorySize, ATTN_SMEM);

    // 1. split x + weights
    split_in_kernel<<<(NX + 4 * NW + 255) / 256, 256>>>(x, Wq, Wk, Wv, Wo);

    // 2. Q,K,V projections (HMMA, double-buffered)
    dim3 gq(49, 6, 3);
    qkv_mm_kernel<<<gq, 256, MM_SMEM>>>();

    // 3. positional softmax (separable, exact)
    dim3 gp1(GRID_S, NHEAD, BATCH);
    pos1_kernel<<<gp1, 256>>>(Wp);
    pos2_kernel<<<gp1, 256>>>(Wp, bp);

    // 4. flash attention (HMMA, double-buffered) + blend -> Oh/Ol
    dim3 ga((NPATCH + AQ - 1) / AQ, NHEAD, BATCH);   // (7, 12, 8)
    attn_kernel<<<ga, 256, ATTN_SMEM>>>(gt);

    // 5. output projection (HMMA, double-buffered)
    dim3 go(49, 6, 1);
    out_mm_kernel<<<go, 256, MM_SMEM>>>(bo, out);
}

// round 16
// speedup vs baseline: 3.5205x; 1.1221x over previous
#include <cuda_runtime.h>
#include <cuda_bf16.h>

#define BATCH   8
#define NPATCH  784
#define EDIM    384
#define NHEAD   12
#define HDIM    32
#define GRID_S  28

#define NX (BATCH * NPATCH * EDIM)   // 2408448
#define NW (EDIM * EDIM)             // 147456

typedef unsigned long long ull;
typedef __nv_bfloat16 bf16;

// -------- scratch (no allocations allowed) --------
__device__ float g_posO[BATCH * NHEAD * NPATCH * HDIM];
__device__ float g_T[BATCH * NHEAD * GRID_S * GRID_S * HDIM];
__device__ float g_Zx[NHEAD * GRID_S];
__device__ bf16 g_Qh[NX], g_Ql[NX];    // pre-scaled by scale*log2e
__device__ bf16 g_Kh[NX], g_Kl[NX];
__device__ bf16 g_Vh[NX], g_Vl[NX];
__device__ bf16 g_Oh[NX], g_Ol[NX];
__device__ bf16 g_Xh[NX], g_Xl[NX];
__device__ bf16 g_Wh[4 * NW], g_Wl[4 * NW];   // Wq, Wk, Wv, Wo

__device__ __forceinline__ float ex2f(float x) {
    float y;
    asm("ex2.approx.f32 %0, %1;" : "=f"(y) : "f"(x));
    return y;
}
__device__ __forceinline__ unsigned packbf2(float lo, float hi) {
    unsigned r;
    asm("cvt.rn.bf16x2.f32 %0, %1, %2;" : "=r"(r) : "f"(hi), "f"(lo));
    return r;
}
__device__ __forceinline__ float bfres(float v) {
    return v - __bfloat162float(__float2bfloat16(v));
}
__device__ __forceinline__ unsigned s2u(const void* p) {
    unsigned a;
    asm("{ .reg .u64 t; cvta.to.shared.u64 t, %1; cvt.u32.u64 %0, t; }" : "=r"(a) : "l"(p));
    return a;
}
__device__ __forceinline__ void cpasync16(unsigned saddr, const void* g) {
    asm volatile("cp.async.cg.shared.global [%0], [%1], 16;" :: "r"(saddr), "l"(g));
}
__device__ __forceinline__ void cp_commit() {
    asm volatile("cp.async.commit_group;" ::: "memory");
}
__device__ __forceinline__ void cp_wait1() {
    asm volatile("cp.async.wait_group 1;" ::: "memory");
}
__device__ __forceinline__ void cp_wait0() {
    asm volatile("cp.async.wait_group 0;" ::: "memory");
}
__device__ __forceinline__ void ldmx2t(unsigned& r0, unsigned& r1, unsigned saddr) {
    asm volatile("ldmatrix.sync.aligned.m8n8.x2.trans.shared.b16 {%0,%1}, [%2];"
                 : "=r"(r0), "=r"(r1) : "r"(saddr));
}
__device__ __forceinline__ void ldmx4(unsigned* r, unsigned saddr) {
    asm volatile("ldmatrix.sync.aligned.m8n8.x4.shared.b16 {%0,%1,%2,%3}, [%4];"
                 : "=r"(r[0]), "=r"(r[1]), "=r"(r[2]), "=r"(r[3]) : "r"(saddr));
}

// -------- warp-level bf16 MMA (validated R13/R14) --------
__device__ __forceinline__ void mma_bf16(float* d, const unsigned* a, const unsigned* b) {
    asm volatile(
        "mma.sync.aligned.m16n8k16.row.col.f32.bf16.bf16.f32 "
        "{%0,%1,%2,%3}, {%4,%5,%6,%7}, {%8,%9}, {%0,%1,%2,%3};"
        : "+f"(d[0]), "+f"(d[1]), "+f"(d[2]), "+f"(d[3])
        : "r"(a[0]), "r"(a[1]), "r"(a[2]), "r"(a[3]), "r"(b[0]), "r"(b[1]));
}

// =====================================================================
// Split fp32 -> (bf16 hi, bf16 lo): x and the four weight matrices.
// =====================================================================
__global__ __launch_bounds__(256) void split_in_kernel(const float* __restrict__ x,
                                                       const float* __restrict__ Wq,
                                                       const float* __restrict__ Wk,
                                                       const float* __restrict__ Wv,
                                                       const float* __restrict__ Wo)
{
    const int i = blockIdx.x * 256 + threadIdx.x;
    const int total = NX + 4 * NW;
    if (i >= total) return;
    float v;
    bf16 *hp, *lp;
    if (i < NX) {
        v = x[i];
        hp = g_Xh + i; lp = g_Xl + i;
    } else {
        int j = i - NX;
        int w = 0;
        while (j >= NW) { j -= NW; w++; }
        const float* src = (w == 0) ? Wq : (w == 1) ? Wk : (w == 2) ? Wv : Wo;
        v = src[j];
        hp = g_Wh + (i - NX); lp = g_Wl + (i - NX);
    }
    const bf16 h = __float2bfloat16(v);
    const bf16 l = __float2bfloat16(v - __bfloat162float(h));
    *hp = h; *lp = l;
}

// =====================================================================
// bf16-split GEMM on HMMA: cp.async double-buffered, ldmatrix.x4 frags.
// CTA 128x64, 8 warps, warp 64x16; math identical to R14/R15.
// =====================================================================
#define MT 128
#define NT 64
#define KT 64
#define SPAD 72
#define SM_A (MT * SPAD)
#define SM_B (NT * SPAD)
#define MM_STAGE (2 * SM_A + 2 * SM_B)      // bf16 elements per stage
#define MM_SMEM (2 * MM_STAGE * 2)          // bytes = 110592

__device__ __forceinline__ void mm_core(const bf16* __restrict__ Ah,
                                        const bf16* __restrict__ Al,
                                        const bf16* __restrict__ Bh,
                                        const bf16* __restrict__ Bl,
                                        const float* __restrict__ bias,
                                        float oscale,
                                        float* __restrict__ Yf,
                                        bf16* __restrict__ Yh,
                                        bf16* __restrict__ Yl)
{
    extern __shared__ __align__(16) unsigned char smraw[];
    const unsigned sbase = s2u(smraw);

    const int t    = threadIdx.x;
    const int wid  = t >> 5;
    const int lane = t & 31;
    const int gid  = lane >> 2;
    const int tig  = lane & 3;
    const int warp_m = (wid & 1) * 64;
    const int warp_n = (wid >> 1) * 16;
    const int row0 = blockIdx.x * MT;
    const int col0 = blockIdx.y * NT;

    // ldmatrix per-thread offsets (bytes, relative to array base in stage)
    // A (x4: matrices (m0,k0),(m8,k0),(m0,k8),(m8,k8))
    const unsigned aoff = (unsigned)(((warp_m + (lane & 7) + ((lane >> 3) & 1) * 8) * SPAD
                                      + ((lane >> 4) & 1) * 8) * 2);
    // B (x4: matrices (n0,k0),(n0,k8),(n8,k0),(n8,k8))
    const unsigned boff = (unsigned)(((warp_n + (lane & 7) + ((lane >> 4) & 1) * 8) * SPAD
                                      + ((lane >> 3) & 1) * 8) * 2);

    float acc[4][2][4];
#pragma unroll
    for (int i = 0; i < 4; i++)
#pragma unroll
        for (int j = 0; j < 2; j++)
#pragma unroll
            for (int c = 0; c < 4; c++) acc[i][j][c] = 0.f;

    auto issue = [&](int kt, int buf) {
        const int kb = kt * KT;
        const unsigned s0 = sbase + (unsigned)buf * (MM_STAGE * 2);
#pragma unroll
        for (int i = 0; i < 4; i++) {
            const int idx = t + i * 256;
            const int r = idx >> 3, c = (idx & 7) * 8;
            const size_t g = (size_t)(row0 + r) * EDIM + kb + c;
            const unsigned off = (unsigned)(r * SPAD + c) * 2;
            cpasync16(s0 + off, &Ah[g]);
            cpasync16(s0 + SM_A * 2 + off, &Al[g]);
        }
#pragma unroll
        for (int i = 0; i < 2; i++) {
            const int idx = t + i * 256;
            const int r = idx >> 3, c = (idx & 7) * 8;
            const size_t g = (size_t)(col0 + r) * EDIM + kb + c;
            const unsigned off = (unsigned)(r * SPAD + c) * 2;
            cpasync16(s0 + (2 * SM_A) * 2 + off, &Bh[g]);
            cpasync16(s0 + (2 * SM_A + SM_B) * 2 + off, &Bl[g]);
        }
        cp_commit();
    };

    issue(0, 0);
    for (int kt = 0; kt < EDIM / KT; kt++) {
        const bool more = (kt + 1 < EDIM / KT);
        if (more) issue(kt + 1, (kt + 1) & 1);
        if (more) cp_wait1(); else cp_wait0();
        __syncthreads();

        const unsigned st = sbase + (unsigned)(kt & 1) * (MM_STAGE * 2);
        const unsigned aBh = st + aoff;
        const unsigned aBl = st + SM_A * 2 + aoff;
        const unsigned bBh = st + (2 * SM_A) * 2 + boff;
        const unsigned bBl = st + (2 * SM_A + SM_B) * 2 + boff;

#pragma unroll
        for (int ks = 0; ks < KT / 16; ks++) {
            const unsigned kso = (unsigned)(ks * 16) * 2;
            unsigned bh4[4], bl4[4];
            ldmx4(bh4, bBh + kso);
            ldmx4(bl4, bBl + kso);
#pragma unroll
            for (int i = 0; i < 4; i++) {
                const unsigned io = (unsigned)(i * 16 * SPAD) * 2 + kso;
                unsigned ah4[4], al4[4];
                ldmx4(ah4, aBh + io);
                ldmx4(al4, aBl + io);
#pragma unroll
                for (int j = 0; j < 2; j++) {
                    mma_bf16(acc[i][j], ah4, &bh4[2 * j]);
                    mma_bf16(acc[i][j], ah4, &bl4[2 * j]);
                    mma_bf16(acc[i][j], al4, &bh4[2 * j]);
                }
            }
        }
        __syncthreads();
    }

#pragma unroll
    for (int i = 0; i < 4; i++) {
        const int row = row0 + warp_m + i * 16 + gid;
#pragma unroll
        for (int j = 0; j < 2; j++) {
            const int col = col0 + warp_n + j * 8 + tig * 2;
            float b0 = 0.f, b1 = 0.f;
            if (bias) { b0 = bias[col]; b1 = bias[col + 1]; }
            const float o0 = fmaf(acc[i][j][0], oscale, b0);
            const float o1 = fmaf(acc[i][j][1], oscale, b1);
            const float o2 = fmaf(acc[i][j][2], oscale, b0);
            const float o3 = fmaf(acc[i][j][3], oscale, b1);
            const size_t e0 = (size_t)row * EDIM + col;
            const size_t e1 = (size_t)(row + 8) * EDIM + col;
            if (Yf) {
                *(float2*)&Yf[e0] = make_float2(o0, o1);
                *(float2*)&Yf[e1] = make_float2(o2, o3);
            }
            if (Yh) {
                *(unsigned*)&Yh[e0] = packbf2(o0, o1);
                *(unsigned*)&Yh[e1] = packbf2(o2, o3);
                *(unsigned*)&Yl[e0] = packbf2(bfres(o0), bfres(o1));
                *(unsigned*)&Yl[e1] = packbf2(bfres(o2), bfres(o3));
            }
        }
    }
}

#define QSCALE 0.41647617814089046f   // 12^-0.5 * log2(e)

__global__ __launch_bounds__(256) void qkv_mm_kernel()
{
    const int z = blockIdx.z;
    bf16* Yh = (z == 0) ? g_Qh : (z == 1) ? g_Kh : g_Vh;
    bf16* Yl = (z == 0) ? g_Ql : (z == 1) ? g_Kl : g_Vl;
    const float sc = (z == 0) ? QSCALE : 1.0f;
    mm_core(g_Xh, g_Xl, g_Wh + (size_t)z * NW, g_Wl + (size_t)z * NW,
            nullptr, sc, nullptr, Yh, Yl);
}

__global__ __launch_bounds__(256) void out_mm_kernel(const float* __restrict__ bo,
                                                     float* __restrict__ Y)
{
    mm_core(g_Oh, g_Ol, g_Wh + 3 * (size_t)NW, g_Wl + 3 * (size_t)NW,
            bo, 1.0f, Y, nullptr, nullptr);
}

// =====================================================================
// Separable positional softmax (EXACT); V reconstructed as Vh+Vl.
// =====================================================================
__global__ __launch_bounds__(256) void pos1_kernel(const float* __restrict__ Wpos)
{
    __shared__ float Vs[GRID_S][HDIM];
    __shared__ float fx[GRID_S][GRID_S];
    __shared__ float Zx[GRID_S];

    const int t  = threadIdx.x;
    const int my = blockIdx.x;
    const int h  = blockIdx.y;
    const int b  = blockIdx.z;
    const float LOG2E = 1.4426950408889634f;
    const float w0 = Wpos[h * 3 + 0];
    const float w2 = Wpos[h * 3 + 2];

    for (int i = t; i < GRID_S * HDIM; i += 256) {
        const int mx = i >> 5, d = i & 31;
        const size_t g = ((size_t)(b * NPATCH + my * GRID_S + mx) * EDIM) + h * HDIM + d;
        Vs[mx][d] = __bfloat162float(g_Vh[g]) + __bfloat162float(g_Vl[g]);
    }
    for (int i = t; i < GRID_S * GRID_S; i += 256) {
        const int qx = i / GRID_S, mx = i % GRID_S;
        const float dx = (float)(mx - qx);
        fx[qx][mx] = fmaf(w2, dx * dx, w0 * dx);
    }
    __syncthreads();
    if (t < GRID_S) {
        float mmax = -1e30f;
#pragma unroll
        for (int mx = 0; mx < GRID_S; mx++) mmax = fmaxf(mmax, fx[t][mx]);
        float z = 0.f;
#pragma unroll
        for (int mx = 0; mx < GRID_S; mx++) {
            const float f = ex2f((fx[t][mx] - mmax) * LOG2E);
            fx[t][mx] = f;
            z += f;
        }
        Zx[t] = z;
        g_Zx[h * GRID_S + t] = z;
    }
    __syncthreads();

    float* Tp = g_T + ((((size_t)(b * NHEAD + h) * GRID_S) * GRID_S) * HDIM);
    for (int i = t; i < GRID_S * HDIM; i += 256) {
        const int qx = i >> 5, d = i & 31;
        float s = 0.f;
#pragma unroll
        for (int mx = 0; mx < GRID_S; mx++) s = fmaf(fx[qx][mx], Vs[mx][d], s);
        Tp[((size_t)qx * GRID_S + my) * HDIM + d] = s;
    }
}

__global__ __launch_bounds__(256) void pos2_kernel(const float* __restrict__ Wpos,
                                                   const float* __restrict__ bpos)
{
    __shared__ float Ts[GRID_S][HDIM];
    __shared__ float fy[GRID_S][GRID_S];
    __shared__ float Zy[GRID_S];

    const int t  = threadIdx.x;
    const int qx = blockIdx.x;
    const int h  = blockIdx.y;
    const int b  = blockIdx.z;
    const float LOG2E = 1.4426950408889634f;
    const float w1 = Wpos[h * 3 + 1];
    const float w2 = Wpos[h * 3 + 2];
    const float bp = bpos[h];

    const float* Tp = g_T + ((((size_t)(b * NHEAD + h) * GRID_S + qx) * GRID_S) * HDIM);
    for (int i = t; i < GRID_S * HDIM; i += 256) {
        Ts[i >> 5][i & 31] = Tp[i];
    }
    for (int i = t; i < GRID_S * GRID_S; i += 256) {
        const int qy = i / GRID_S, my = i % GRID_S;
        const float dy = (float)(my - qy);
        fy[qy][my] = fmaf(w2, dy * dy, w1 * dy) + bp;
    }
    __syncthreads();
    if (t < GRID_S) {
        float mmax = -1e30f;
#pragma unroll
        for (int my = 0; my < GRID_S; my++) mmax = fmaxf(mmax, fy[t][my]);
        float z = 0.f;
#pragma unroll
        for (int my = 0; my < GRID_S; my++) {
            const float f = ex2f((fy[t][my] - mmax) * LOG2E);
            fy[t][my] = f;
            z += f;
        }
        Zy[t] = z;
    }
    __syncthreads();

    const float zx = g_Zx[h * GRID_S + qx];
    for (int i = t; i < GRID_S * HDIM; i += 256) {
        const int qy = i >> 5, d = i & 31;
        float s = 0.f;
#pragma unroll
        for (int my = 0; my < GRID_S; my++) s = fmaf(fy[qy][my], Ts[my][d], s);
        const int n = qy * GRID_S + qx;
        g_posO[(((size_t)(b * NHEAD + h) * NPATCH + n) * HDIM) + d] = s / (zx * Zy[qy]);
    }
}

// =====================================================================
// Flash attention on HMMA: cp.async double-buffered K/V, ldmatrix.x4 K
// fragments, ldmatrix.trans V fragments. Q pre-scaled by scale*log2e.
// =====================================================================
#define AQ 128
#define AK 112
#define KPAD 40
#define A_ONE (AK * KPAD)               // bf16 elems per array (4480)
#define A_STAGE (4 * A_ONE)             // Kh,Kl,Vh,Vl
#define ATTN_SMEM (2 * A_STAGE * 2)     // bytes = 71680

__global__ __launch_bounds__(256) void attn_kernel(const float* __restrict__ gating)
{
    extern __shared__ __align__(16) unsigned char smraw[];
    const unsigned sbase = s2u(smraw);

    const int t    = threadIdx.x;
    const int wid  = t >> 5;
    const int lane = t & 31;
    const int gid  = lane >> 2;
    const int tig  = lane & 3;
    const int h  = blockIdx.y;
    const int b  = blockIdx.z;
    const int n0 = blockIdx.x * AQ;

    // ---- Q fragments (pre-scaled) ----
    const int r0 = n0 + wid * 16 + gid;
    const int rq0 = (r0 < NPATCH) ? r0 : (NPATCH - 1);
    const int rq1 = (r0 + 8 < NPATCH) ? (r0 + 8) : (NPATCH - 1);
    const size_t qb0 = (size_t)(b * NPATCH + rq0) * EDIM + h * HDIM;
    const size_t qb1 = (size_t)(b * NPATCH + rq1) * EDIM + h * HDIM;
    unsigned qh[2][4], ql[2][4];
#pragma unroll
    for (int ks = 0; ks < 2; ks++) {
        const int c = tig * 2 + ks * 16;
        qh[ks][0] = *(const unsigned*)&g_Qh[qb0 + c];
        qh[ks][1] = *(const unsigned*)&g_Qh[qb1 + c];
        qh[ks][2] = *(const unsigned*)&g_Qh[qb0 + c + 8];
        qh[ks][3] = *(const unsigned*)&g_Qh[qb1 + c + 8];
        ql[ks][0] = *(const unsigned*)&g_Ql[qb0 + c];
        ql[ks][1] = *(const unsigned*)&g_Ql[qb1 + c];
        ql[ks][2] = *(const unsigned*)&g_Ql[qb0 + c + 8];
        ql[ks][3] = *(const unsigned*)&g_Ql[qb1 + c + 8];
    }

    // K ldmatrix.x4 per-thread offset: row = (lane&7), k-col = (lane>>3)*8
    const unsigned kfoff = (unsigned)(((lane & 7) * KPAD + (lane >> 3) * 8) * 2);

    float O[4][4];
#pragma unroll
    for (int j = 0; j < 4; j++)
#pragma unroll
        for (int c = 0; c < 4; c++) O[j][c] = 0.f;
    float zp0 = 0.f, zp1 = 0.f;

    auto issue = [&](int m0, int buf) {
        const unsigned s0 = sbase + (unsigned)buf * (A_STAGE * 2);
#pragma unroll
        for (int i = 0; i < 7; i++) {
            const int idx = t + i * 256;           // 0..1791
            const int arr = idx / 448;             // 0 Kh, 1 Kl, 2 Vh, 3 Vl
            const int rem = idx - arr * 448;
            const int r = rem >> 2, c = (rem & 3) * 8;
            const size_t g = (size_t)(b * NPATCH + m0 + r) * EDIM + h * HDIM + c;
            const bf16* src = (arr == 0) ? g_Kh : (arr == 1) ? g_Kl
                            : (arr == 2) ? g_Vh : g_Vl;
            cpasync16(s0 + (unsigned)(arr * A_ONE + r * KPAD + c) * 2, &src[g]);
        }
        cp_commit();
    };

    issue(0, 0);
    for (int mt = 0; mt < 7; mt++) {
        const bool more = (mt + 1 < 7);
        if (more) issue((mt + 1) * AK, (mt + 1) & 1);
        if (more) cp_wait1(); else cp_wait0();
        __syncthreads();

        const unsigned st  = sbase + (unsigned)(mt & 1) * (A_STAGE * 2);
        const unsigned khb = st + kfoff;
        const unsigned klb = st + (unsigned)A_ONE * 2 + kfoff;
        const unsigned vhb = st + (unsigned)(2 * A_ONE) * 2;
        const unsigned vlb = st + (unsigned)(3 * A_ONE) * 2;

        // ---- S = Q K^T (ldmatrix.x4: r0,r1 = ks0 b-frag; r2,r3 = ks1) ----
        float S[14][4];
#pragma unroll
        for (int j = 0; j < 14; j++)
#pragma unroll
            for (int c = 0; c < 4; c++) S[j][c] = 0.f;
#pragma unroll
        for (int j = 0; j < 14; j++) {
            const unsigned jo = (unsigned)(j * 8 * KPAD) * 2;
            unsigned k4h[4], k4l[4];
            ldmx4(k4h, khb + jo);
            ldmx4(k4l, klb + jo);
            mma_bf16(S[j], qh[0], &k4h[0]);
            mma_bf16(S[j], ql[0], &k4h[0]);
            mma_bf16(S[j], qh[0], &k4l[0]);
            mma_bf16(S[j], qh[1], &k4h[2]);
            mma_bf16(S[j], ql[1], &k4h[2]);
            mma_bf16(S[j], qh[1], &k4l[2]);
        }

        // ---- softmax weights + AV ----
#pragma unroll
        for (int ks2 = 0; ks2 < 7; ks2++) {
            const int j0 = 2 * ks2, j1 = j0 + 1;
            float w00 = ex2f(S[j0][0]), w01 = ex2f(S[j0][1]);
            float w02 = ex2f(S[j0][2]), w03 = ex2f(S[j0][3]);
            float w10 = ex2f(S[j1][0]), w11 = ex2f(S[j1][1]);
            float w12 = ex2f(S[j1][2]), w13 = ex2f(S[j1][3]);
            zp0 += (w00 + w01) + (w10 + w11);
            zp1 += (w02 + w03) + (w12 + w13);
            unsigned aPh[4], aPl[4];
            aPh[0] = packbf2(w00, w01);
            aPh[1] = packbf2(w02, w03);
            aPh[2] = packbf2(w10, w11);
            aPh[3] = packbf2(w12, w13);
            aPl[0] = packbf2(bfres(w00), bfres(w01));
            aPl[1] = packbf2(bfres(w02), bfres(w03));
            aPl[2] = packbf2(bfres(w10), bfres(w11));
            aPl[3] = packbf2(bfres(w12), bfres(w13));
            const unsigned krow = (unsigned)((ks2 * 16 + (lane & 15)) * KPAD) * 2;
#pragma unroll
            for (int jd = 0; jd < 4; jd++) {
                unsigned vbh[2], vbl[2];
                ldmx2t(vbh[0], vbh[1], vhb + krow + (unsigned)(jd * 8) * 2);
                ldmx2t(vbl[0], vbl[1], vlb + krow + (unsigned)(jd * 8) * 2);
                mma_bf16(O[jd], aPh, vbh);
                mma_bf16(O[jd], aPl, vbh);
                mma_bf16(O[jd], aPh, vbl);
            }
        }
        __syncthreads();
    }

    zp0 += __shfl_xor_sync(0xffffffffu, zp0, 1);
    zp0 += __shfl_xor_sync(0xffffffffu, zp0, 2);
    zp1 += __shfl_xor_sync(0xffffffffu, zp1, 1);
    zp1 += __shfl_xor_sync(0xffffffffu, zp1, 2);

    const float g  = gating[h];
    const float sg = 1.f / (1.f + ex2f(-g * 1.4426950408889634f));
    const float cP0 = (1.f - sg) / zp0;
    const float cP1 = (1.f - sg) / zp1;

    const int rw0 = n0 + wid * 16 + gid;
    const int rw1 = rw0 + 8;
#pragma unroll
    for (int jd = 0; jd < 4; jd++) {
        const int d = jd * 8 + tig * 2;
        if (rw0 < NPATCH) {
            const float2 ps = *(const float2*)&g_posO[(((size_t)(b * NHEAD + h) * NPATCH + rw0) * HDIM) + d];
            const float o0 = fmaf(cP0, O[jd][0], sg * ps.x);
            const float o1 = fmaf(cP0, O[jd][1], sg * ps.y);
            const size_t e = (size_t)(b * NPATCH + rw0) * EDIM + h * HDIM + d;
            *(unsigned*)&g_Oh[e] = packbf2(o0, o1);
            *(unsigned*)&g_Ol[e] = packbf2(bfres(o0), bfres(o1));
        }
        if (rw1 < NPATCH) {
            const float2 ps = *(const float2*)&g_posO[(((size_t)(b * NHEAD + h) * NPATCH + rw1) * HDIM) + d];
            const float o2 = fmaf(cP1, O[jd][2], sg * ps.x);
            const float o3 = fmaf(cP1, O[jd][3], sg * ps.y);
            const size_t e = (size_t)(b * NPATCH + rw1) * EDIM + h * HDIM + d;
            *(unsigned*)&g_Oh[e] = packbf2(o2, o3);
            *(unsigned*)&g_Ol[e] = packbf2(bfres(o2), bfres(o3));
        }
    }
}

// =====================================================================
extern "C" void kernel_launch(void* const* d_in, const int* in_sizes, int n_in,
                              void* d_out, int out_size)
{
    const float* x   = (const float*)d_in[0];
    const float* Wq  = (const float*)d_in[1];
    const float* Wk  = (const float*)d_in[2];
    const float* Wv  = (const float*)d_in[3];
    const float* Wp  = (const float*)d_in[4];
    const float* bp  = (const float*)d_in[5];
    const float* Wo  = (const float*)d_in[6];
    const float* bo  = (const float*)d_in[7];
    const float* gt  = (const float*)d_in[8];
    float* out = (float*)d_out;

    cudaFuncSetAttribute(qkv_mm_kernel, cudaFuncAttributeMaxDynamicSharedMemorySize, MM_SMEM);
    cudaFuncSetAttribute(out_mm_kernel, cudaFuncAttributeMaxDynamicSharedMemorySize, MM_SMEM);
    cudaFuncSetAttribute(attn_kernel, cudaFuncAttributeMaxDynamicSharedMemorySize, ATTN_SMEM);

    // 1. split x + weights
    split_in_kernel<<<(NX + 4 * NW + 255) / 256, 256>>>(x, Wq, Wk, Wv, Wo);

    // 2. Q,K,V projections (HMMA, double-buffered, ldmatrix)
    dim3 gq(49, 6, 3);
    qkv_mm_kernel<<<gq, 256, MM_SMEM>>>();

    // 3. positional softmax (separable, exact)
    dim3 gp1(GRID_S, NHEAD, BATCH);
    pos1_kernel<<<gp1, 256>>>(Wp);
    pos2_kernel<<<gp1, 256>>>(Wp, bp);

    // 4. flash attention (HMMA) + blend -> Oh/Ol
    dim3 ga((NPATCH + AQ - 1) / AQ, NHEAD, BATCH);   // (7, 12, 8)
    attn_kernel<<<ga, 256, ATTN_SMEM>>>(gt);

    // 5. output projection (HMMA)
    dim3 go(49, 6, 1);
    out_mm_kernel<<<go, 256, MM_SMEM>>>(bo, out);
}